// round 10
// baseline (speedup 1.0000x reference)
#include <cuda_runtime.h>
#include <math.h>
#include <stdint.h>

#define N_ROWS 131072
#define DIM    512
#define NGRP   4096
#define EPSV   1e-12f

// ---------------- scratch (static device arrays; no allocation allowed) ----------------
// NOTE: g_xs, g_wc, g_y are stored K-INTERLEAVED: within each 32-float k-chunk,
// float k sits at position (k&3)*8 + ((k>>2)&7). This makes every mma-fragment
// load a contiguous 16B LDS.128 in the GEMM mainloops.
__device__ float g_xs    [(size_t)N_ROWS * DIM];   // 256 MiB: tf32, sorted, k-interleaved
__device__ float g_wc    [3][DIM * DIM];           // tf32, k-interleaved Wg, Wf, Wh
__device__ float g_num   [NGRP * DIM];             // segment sums: feats*exp(l)
__device__ float g_den   [NGRP * DIM];             // segment sums: exp(l)
__device__ float g_y     [NGRP * DIM];             // aggregate (tf32, k-interleaved)
__device__ float g_outg  [NGRP * DIM];
__device__ int   g_counts [NGRP];
__device__ int   g_offsets[NGRP + 1];
__device__ int   g_cursor [NGRP];
__device__ int   g_perm   [N_ROWS];
__device__ int   g_gids   [N_ROWS];                // sorted group id per sorted row

// ====================== helpers ======================
__device__ __forceinline__ uint32_t smem_u32(const void* p) {
    uint32_t a;
    asm("{ .reg .u64 t; cvta.to.shared.u64 t, %1; cvt.u32.u64 %0, t; }" : "=r"(a) : "l"(p));
    return a;
}
__device__ __forceinline__ void cpa16(uint32_t dst, const void* src) {
    asm volatile("cp.async.cg.shared.global [%0], [%1], 16;" :: "r"(dst), "l"(src) : "memory");
}
__device__ __forceinline__ float tf32r(float x) {
    uint32_t u;
    asm("cvt.rna.tf32.f32 %0, %1;" : "=r"(u) : "f"(x));
    return __uint_as_float(u);
}
__device__ __forceinline__ void mma8(float* d, uint32_t a0, uint32_t a1, uint32_t a2,
                                     uint32_t a3, uint32_t b0, uint32_t b1) {
    asm volatile(
        "mma.sync.aligned.m16n8k8.row.col.f32.tf32.tf32.f32 "
        "{%0,%1,%2,%3}, {%4,%5,%6,%7}, {%8,%9}, {%0,%1,%2,%3};"
        : "+f"(d[0]), "+f"(d[1]), "+f"(d[2]), "+f"(d[3])
        : "r"(a0), "r"(a1), "r"(a2), "r"(a3), "r"(b0), "r"(b1));
}
#define FU(x) __float_as_uint(x)

// k-interleave position within a 32-float chunk
__device__ __forceinline__ int kperm(int k) { return (k & ~31) + ((k & 3) * 8) + ((k >> 2) & 7); }

// ====================== GEMM tiling constants ======================
#define KC      32
#define CHUNKS  (DIM / KC)          // 16
#define STG     3
#define SA      36                  // floats per smem row (KC + 4 pad); 144B, 16B-aligned
#define ATF     (128 * SA)
#define STGF    (2 * ATF)           // A 128 rows + B 128 rows
#define SMEM_B  (STG * STGF * 4)    // 110592 bytes
#define EST     133                 // epilogue staging stride

// 128 rows x KC floats (gmem already k-interleaved; plain contiguous copy)
__device__ __forceinline__ void load_tile_A(uint32_t dst, const float* src, int k0, int t) {
    #pragma unroll
    for (int j = 0; j < 4; j++) {
        int idx = j * 256 + t;
        int row = idx >> 3, seg = idx & 7;
        cpa16(dst + row * (SA * 4) + seg * 16,
              src + (size_t)row * DIM + k0 + seg * 4);
    }
}
// B tile: rows 0..63 = Wg[n0..], rows 64..127 = Wf[n0..]
__device__ __forceinline__ void load_tile_B2(uint32_t dst, const float* Wg, const float* Wf,
                                             int n0, int k0, int t) {
    #pragma unroll
    for (int j = 0; j < 4; j++) {
        int idx = j * 256 + t;
        int row = idx >> 3, seg = idx & 7;
        const float* base = (row < 64) ? (Wg + (size_t)(n0 + row) * DIM)
                                       : (Wf + (size_t)(n0 + row - 64) * DIM);
        cpa16(dst + row * (SA * 4) + seg * 16, base + k0 + seg * 4);
    }
}

// ====================== fused dual-GEMM + softmax segment-reduce ======================
// grid (8, 1024): n0 = bx*64, m0 = by*128. Warp tile: M32(wr) x N32(wc) x both matrices.
__global__ __launch_bounds__(256, 2) void gemm_fused(
    const float* __restrict__ bg_, const float* __restrict__ bf_)
{
    extern __shared__ float sm[];
    const uint32_t sb = smem_u32(sm);
    const int t = threadIdx.x;
    const int wid = t >> 5, lid = t & 31;
    const int g = lid >> 2, c = lid & 3;
    const int wr = wid & 3, wc = wid >> 2;

    const int n0 = blockIdx.x * 64;
    const int m0 = blockIdx.y * 128;
    const float* Ab = g_xs + (size_t)m0 * DIM;
    const float* Wg = g_wc[0];
    const float* Wf = g_wc[1];

    float accg[2][4][4], accf[2][4][4];
    #pragma unroll
    for (int mf = 0; mf < 2; mf++)
        #pragma unroll
        for (int nf = 0; nf < 4; nf++)
            #pragma unroll
            for (int q = 0; q < 4; q++) { accg[mf][nf][q] = 0.f; accf[mf][nf][q] = 0.f; }

    #pragma unroll
    for (int cc = 0; cc < STG - 1; cc++) {
        load_tile_A(sb + cc * STGF * 4, Ab, cc * KC, t);
        load_tile_B2(sb + cc * STGF * 4 + ATF * 4, Wg, Wf, n0, cc * KC, t);
        asm volatile("cp.async.commit_group;" ::: "memory");
    }

    for (int i = 0; i < CHUNKS; i++) {
        asm volatile("cp.async.wait_group 1;" ::: "memory");
        __syncthreads();
        int nxt = i + STG - 1;
        if (nxt < CHUNKS) {
            int s = nxt % STG;
            load_tile_A(sb + s * STGF * 4, Ab, nxt * KC, t);
            load_tile_B2(sb + s * STGF * 4 + ATF * 4, Wg, Wf, n0, nxt * KC, t);
        }
        asm volatile("cp.async.commit_group;" ::: "memory");

        const float* As = sm + (i % STG) * STGF + (wr * 32) * SA;
        const float* Bs = sm + (i % STG) * STGF + ATF + (wc * 32) * SA;
        #pragma unroll
        for (int kh = 0; kh < 2; kh++) {
            // per-thread contiguous fragment loads (LDS.128, conflict-free)
            float4 alo[2], ahi[2];
            #pragma unroll
            for (int mf = 0; mf < 2; mf++) {
                alo[mf] = *(const float4*)(As + (mf * 16 + g) * SA + c * 8 + kh * 4);
                ahi[mf] = *(const float4*)(As + (mf * 16 + g + 8) * SA + c * 8 + kh * 4);
            }
            #pragma unroll
            for (int nf = 0; nf < 4; nf++) {
                float4 bgv = *(const float4*)(Bs + (nf * 8 + g) * SA + c * 8 + kh * 4);
                float4 bfv = *(const float4*)(Bs + (64 + nf * 8 + g) * SA + c * 8 + kh * 4);
                // sub-step s=0: floats {x,y}; s=1: floats {z,w}
                #pragma unroll
                for (int mf = 0; mf < 2; mf++) {
                    mma8(accg[mf][nf], FU(alo[mf].x), FU(ahi[mf].x), FU(alo[mf].y), FU(ahi[mf].y),
                         FU(bgv.x), FU(bgv.y));
                    mma8(accf[mf][nf], FU(alo[mf].x), FU(ahi[mf].x), FU(alo[mf].y), FU(ahi[mf].y),
                         FU(bfv.x), FU(bfv.y));
                    mma8(accg[mf][nf], FU(alo[mf].z), FU(ahi[mf].z), FU(alo[mf].w), FU(ahi[mf].w),
                         FU(bgv.z), FU(bgv.w));
                    mma8(accf[mf][nf], FU(alo[mf].z), FU(ahi[mf].z), FU(alo[mf].w), FU(ahi[mf].w),
                         FU(bfv.z), FU(bfv.w));
                }
            }
        }
    }
    __syncthreads();

    // ---- epilogue: stage (l, f) transposed [col][row], stride EST ----
    float* sl = sm;
    float* sf = sm + 64 * EST;
    int* sgid = (int*)(sm + 2 * 64 * EST);
    if (t < 128) sgid[t] = g_gids[m0 + t];
    #pragma unroll
    for (int nf = 0; nf < 4; nf++) {
        int cb = wc * 32 + nf * 8 + c * 2;
        float2 bgv = *(const float2*)(bg_ + n0 + cb);
        float2 bfv = *(const float2*)(bf_ + n0 + cb);
        #pragma unroll
        for (int mf = 0; mf < 2; mf++) {
            int r0 = wr * 32 + mf * 16 + g;
            sl[cb * EST + r0]           = accg[mf][nf][0] + bgv.x;
            sl[(cb + 1) * EST + r0]     = accg[mf][nf][1] + bgv.y;
            sl[cb * EST + r0 + 8]       = accg[mf][nf][2] + bgv.x;
            sl[(cb + 1) * EST + r0 + 8] = accg[mf][nf][3] + bgv.y;
            sf[cb * EST + r0]           = accf[mf][nf][0] + bfv.x;
            sf[(cb + 1) * EST + r0]     = accf[mf][nf][1] + bfv.y;
            sf[cb * EST + r0 + 8]       = accf[mf][nf][2] + bfv.x;
            sf[(cb + 1) * EST + r0 + 8] = accf[mf][nf][3] + bfv.y;
        }
    }
    __syncthreads();

    // ---- segmented reduce over sorted rows; flush per group via atomics ----
    {
        int col = t & 63, q = t >> 6;
        int gcol = n0 + col;
        int r = q * 32;
        int curg = sgid[r];
        float num = 0.f, den = 0.f;
        #pragma unroll 1
        for (int k = 0; k < 32; k++, r++) {
            int gg = sgid[r];
            float l = sl[col * EST + r];
            float f = sf[col * EST + r];
            float e = __expf(l);
            if (gg != curg) {
                atomicAdd(&g_num[(size_t)curg * DIM + gcol], num);
                atomicAdd(&g_den[(size_t)curg * DIM + gcol], den);
                num = 0.f; den = 0.f; curg = gg;
            }
            num += f * e;
            den += e;
        }
        atomicAdd(&g_num[(size_t)curg * DIM + gcol], num);
        atomicAdd(&g_den[(size_t)curg * DIM + gcol], den);
    }
}

// ====================== GEMM3: out_group = y @ Wh^T + bh ======================
// grid (4, 32), CTA 128x128. Warp tile M32(wr) x N64(wc).
__global__ __launch_bounds__(256, 2) void gemm_mma3(const float* __restrict__ bias)
{
    extern __shared__ float sm[];
    const uint32_t sb = smem_u32(sm);
    const int t = threadIdx.x;
    const int wid = t >> 5, lid = t & 31;
    const int g = lid >> 2, c = lid & 3;
    const int wr = wid & 3, wc = wid >> 2;

    const int m0 = blockIdx.y * 128, n0 = blockIdx.x * 128;
    const float* Ab = g_y + (size_t)m0 * DIM;
    const float* Wb = g_wc[2] + (size_t)n0 * DIM;
    float* C = g_outg;

    float acc[2][8][4];
    #pragma unroll
    for (int mf = 0; mf < 2; mf++)
        #pragma unroll
        for (int nf = 0; nf < 8; nf++)
            #pragma unroll
            for (int q = 0; q < 4; q++) acc[mf][nf][q] = 0.f;

    #pragma unroll
    for (int cc = 0; cc < STG - 1; cc++) {
        load_tile_A(sb + cc * STGF * 4,           Ab, cc * KC, t);
        load_tile_A(sb + cc * STGF * 4 + ATF * 4, Wb, cc * KC, t);
        asm volatile("cp.async.commit_group;" ::: "memory");
    }

    for (int i = 0; i < CHUNKS; i++) {
        asm volatile("cp.async.wait_group 1;" ::: "memory");
        __syncthreads();
        int nxt = i + STG - 1;
        if (nxt < CHUNKS) {
            int s = nxt % STG;
            load_tile_A(sb + s * STGF * 4,           Ab, nxt * KC, t);
            load_tile_A(sb + s * STGF * 4 + ATF * 4, Wb, nxt * KC, t);
        }
        asm volatile("cp.async.commit_group;" ::: "memory");

        const float* As = sm + (i % STG) * STGF + (wr * 32) * SA;
        const float* Bs = sm + (i % STG) * STGF + ATF + (wc * 64) * SA;
        #pragma unroll
        for (int kh = 0; kh < 2; kh++) {
            float4 alo[2], ahi[2];
            #pragma unroll
            for (int mf = 0; mf < 2; mf++) {
                alo[mf] = *(const float4*)(As + (mf * 16 + g) * SA + c * 8 + kh * 4);
                ahi[mf] = *(const float4*)(As + (mf * 16 + g + 8) * SA + c * 8 + kh * 4);
            }
            #pragma unroll
            for (int nf = 0; nf < 8; nf++) {
                float4 bv = *(const float4*)(Bs + (nf * 8 + g) * SA + c * 8 + kh * 4);
                #pragma unroll
                for (int mf = 0; mf < 2; mf++) {
                    mma8(acc[mf][nf], FU(alo[mf].x), FU(ahi[mf].x), FU(alo[mf].y), FU(ahi[mf].y),
                         FU(bv.x), FU(bv.y));
                    mma8(acc[mf][nf], FU(alo[mf].z), FU(ahi[mf].z), FU(alo[mf].w), FU(ahi[mf].w),
                         FU(bv.z), FU(bv.w));
                }
            }
        }
    }

    const int rowb = m0 + wr * 32 + g;
    const int colb = n0 + wc * 64 + c * 2;
    #pragma unroll
    for (int nf = 0; nf < 8; nf++) {
        int col = colb + nf * 8;
        float bv0 = bias[col], bv1 = bias[col + 1];
        #pragma unroll
        for (int mf = 0; mf < 2; mf++) {
            int r0 = rowb + mf * 16;
            float2 v;
            v.x = acc[mf][nf][0] + bv0; v.y = acc[mf][nf][1] + bv1;
            *(float2*)(C + (size_t)r0 * DIM + col) = v;
            v.x = acc[mf][nf][2] + bv0; v.y = acc[mf][nf][3] + bv1;
            *(float2*)(C + (size_t)(r0 + 8) * DIM + col) = v;
        }
    }
}

// ---------------- small kernels ----------------
__global__ void zero_counts_k() {
    int i = blockIdx.x * blockDim.x + threadIdx.x;
    if (i < NGRP) g_counts[i] = 0;
}
__global__ void zero_nd_k() {
    int i = blockIdx.x * blockDim.x + threadIdx.x;
    if (i < NGRP * DIM / 4) {
        float4 z = make_float4(0.f, 0.f, 0.f, 0.f);
        ((float4*)g_num)[i] = z;
        ((float4*)g_den)[i] = z;
    }
}
__global__ void hist_k(const int* __restrict__ jx) {
    int i = blockIdx.x * blockDim.x + threadIdx.x;
    if (i < N_ROWS) atomicAdd(&g_counts[jx[i]], 1);
}
__global__ void scan_k() {
    __shared__ int s[NGRP];
    __shared__ int ps[1024];
    int t = threadIdx.x;
    for (int i = t; i < NGRP; i += 1024) s[i] = g_counts[i];
    __syncthreads();
    int b = t * 4;
    int v0 = s[b], v1 = s[b + 1], v2 = s[b + 2], v3 = s[b + 3];
    int sum = v0 + v1 + v2 + v3;
    ps[t] = sum;
    __syncthreads();
    #pragma unroll
    for (int off = 1; off < 1024; off <<= 1) {
        int x = (t >= off) ? ps[t - off] : 0;
        __syncthreads();
        ps[t] += x;
        __syncthreads();
    }
    int excl = ps[t] - sum;
    int o0 = excl, o1 = o0 + v0, o2 = o1 + v1, o3 = o2 + v2;
    g_offsets[b] = o0;     g_offsets[b + 1] = o1;
    g_offsets[b + 2] = o2; g_offsets[b + 3] = o3;
    g_cursor[b] = o0;      g_cursor[b + 1] = o1;
    g_cursor[b + 2] = o2;  g_cursor[b + 3] = o3;
    if (t == 1023) g_offsets[NGRP] = o3 + v3;
}
__global__ void scatter_k(const int* __restrict__ jx) {
    int i = blockIdx.x * blockDim.x + threadIdx.x;
    if (i < N_ROWS) {
        int g = jx[i];
        int pos = atomicAdd(&g_cursor[g], 1);
        g_perm[pos] = i;
        g_gids[pos] = g;
    }
}

// permuted tf32 convert + k-interleave: g_xs[r][kperm(k)] = tf32(x[perm[r]][k])
__global__ void conv_xs_k(const float4* __restrict__ x) {
    int idx = blockIdx.x * blockDim.x + threadIdx.x;
    if (idx < N_ROWS * (DIM / 4)) {
        int r = idx >> 7, cc = idx & 127;
        int src = g_perm[r];
        float4 v = x[((size_t)src << 7) + cc];
        float* dst = g_xs + (size_t)r * DIM;
        int k = cc * 4;
        dst[kperm(k + 0)] = tf32r(v.x);
        dst[kperm(k + 1)] = tf32r(v.y);
        dst[kperm(k + 2)] = tf32r(v.z);
        dst[kperm(k + 3)] = tf32r(v.w);
    }
}
__global__ void conv_w_k(const float4* __restrict__ Wg, const float4* __restrict__ Wf,
                         const float4* __restrict__ Wh) {
    int i = blockIdx.x * blockDim.x + threadIdx.x;
    const int per = DIM * DIM / 4;
    if (i < 3 * per) {
        int mat = i / per, j = i % per;
        const float4* src = (mat == 0) ? Wg : (mat == 1) ? Wf : Wh;
        float4 v = src[j];
        int row = j >> 7, cc = j & 127;
        float* dst = g_wc[mat] + (size_t)row * DIM;
        int k = cc * 4;
        dst[kperm(k + 0)] = tf32r(v.x);
        dst[kperm(k + 1)] = tf32r(v.y);
        dst[kperm(k + 2)] = tf32r(v.z);
        dst[kperm(k + 3)] = tf32r(v.w);
    }
}

// y = num / (den + eps), tf32-rounded + k-interleaved for GEMM3
__global__ void norm_y_k() {
    int i = blockIdx.x * blockDim.x + threadIdx.x;
    if (i < NGRP * DIM) {
        int row = i >> 9, d = i & 511;
        g_y[(size_t)row * DIM + kperm(d)] = tf32r(g_num[i] / (g_den[i] + EPSV));
    }
}

// out[i,:] = outg[jx[i],:]
__global__ void gather_k(const int* __restrict__ jx, float4* __restrict__ out) {
    int idx = blockIdx.x * blockDim.x + threadIdx.x;
    if (idx < N_ROWS * (DIM / 4)) {
        int i = idx >> 7;
        int c = idx & 127;
        out[idx] = ((const float4*)g_outg)[((size_t)jx[i] << 7) + c];
    }
}

extern "C" void kernel_launch(void* const* d_in, const int* in_sizes, int n_in,
                              void* d_out, int out_size) {
    const float* x  = (const float*)d_in[0];
    const float* Wf = (const float*)d_in[1];
    const float* bf = (const float*)d_in[2];
    const float* Wg = (const float*)d_in[3];
    const float* bg = (const float*)d_in[4];
    const float* Wh = (const float*)d_in[5];
    const float* bh = (const float*)d_in[6];
    const int*   jx = (const int*)d_in[7];
    float* out = (float*)d_out;
    (void)in_sizes; (void)n_in; (void)out_size;

    cudaFuncSetAttribute(gemm_fused, cudaFuncAttributeMaxDynamicSharedMemorySize, SMEM_B);
    cudaFuncSetAttribute(gemm_mma3,  cudaFuncAttributeMaxDynamicSharedMemorySize, SMEM_B);

    // zero accumulators + counting sort of jx
    zero_counts_k<<<(NGRP + 255) / 256, 256>>>();
    zero_nd_k<<<(NGRP * DIM / 4 + 255) / 256, 256>>>();
    hist_k<<<(N_ROWS + 255) / 256, 256>>>(jx);
    scan_k<<<1, 1024>>>();
    scatter_k<<<(N_ROWS + 255) / 256, 256>>>(jx);

    // tf32 pre-conversion (x permuted into sorted order; all k-interleaved)
    conv_w_k<<<(3 * DIM * DIM / 4 + 255) / 256, 256>>>(
        (const float4*)Wg, (const float4*)Wf, (const float4*)Wh);
    conv_xs_k<<<(N_ROWS * (DIM / 4) + 255) / 256, 256>>>((const float4*)x);

    // fused dual GEMM + softmax segment-reduce
    gemm_fused<<<dim3(8, N_ROWS / 128), 256, SMEM_B>>>(bg, bf);

    // y = num/(den+eps)
    norm_y_k<<<(NGRP * DIM + 255) / 256, 256>>>();

    // out_group = y @ Wh^T + bh
    gemm_mma3<<<dim3(4, NGRP / 128), 256, SMEM_B>>>(bh);

    // out = out_group[jx]
    gather_k<<<(N_ROWS * (DIM / 4) + 255) / 256, 256>>>(jx, (float4*)out);
}

// round 11
// speedup vs baseline: 1.0784x; 1.0784x over previous
#include <cuda_runtime.h>
#include <math.h>
#include <stdint.h>

#define N_ROWS 131072
#define DIM    512
#define NGRP   4096
#define EPSV   1e-12f

// ---------------- scratch (static device arrays; no allocation allowed) ----------------
__device__ float g_xs    [(size_t)N_ROWS * DIM];   // 256 MiB: tf32-rounded, group-sorted x
__device__ float g_wc    [3][DIM * DIM];           // tf32-rounded Wg, Wf, Wh
__device__ float g_num   [NGRP * DIM];             // segment sums: feats*exp(l)
__device__ float g_den   [NGRP * DIM];             // segment sums: exp(l)
__device__ float g_y     [NGRP * DIM];             // normalized aggregate (tf32-rounded)
__device__ float g_outg  [NGRP * DIM];
__device__ int   g_counts [NGRP];
__device__ int   g_offsets[NGRP + 1];
__device__ int   g_cursor [NGRP];
__device__ int   g_perm   [N_ROWS];
__device__ int   g_gids   [N_ROWS];                // sorted group id per sorted row

// ====================== helpers ======================
__device__ __forceinline__ uint32_t smem_u32(const void* p) {
    uint32_t a;
    asm("{ .reg .u64 t; cvta.to.shared.u64 t, %1; cvt.u32.u64 %0, t; }" : "=r"(a) : "l"(p));
    return a;
}
__device__ __forceinline__ void cpa16(uint32_t dst, const void* src) {
    asm volatile("cp.async.cg.shared.global [%0], [%1], 16;" :: "r"(dst), "l"(src) : "memory");
}
__device__ __forceinline__ float tf32r(float x) {
    uint32_t u;
    asm("cvt.rna.tf32.f32 %0, %1;" : "=r"(u) : "f"(x));
    return __uint_as_float(u);
}
__device__ __forceinline__ void mma8(float* d, const uint32_t* a, uint32_t b0, uint32_t b1) {
    asm volatile(
        "mma.sync.aligned.m16n8k8.row.col.f32.tf32.tf32.f32 "
        "{%0,%1,%2,%3}, {%4,%5,%6,%7}, {%8,%9}, {%0,%1,%2,%3};"
        : "+f"(d[0]), "+f"(d[1]), "+f"(d[2]), "+f"(d[3])
        : "r"(a[0]), "r"(a[1]), "r"(a[2]), "r"(a[3]), "r"(b0), "r"(b1));
}

// ====================== GEMM tiling constants ======================
#define KC      32
#define CHUNKS  (DIM / KC)          // 16
#define STG     3
#define SA      36                  // floats per smem row (KC + 4 pad)
// fused kernel: A tile 256 rows + B tile 128 rows (64 Wg + 64 Wf) per stage
#define ATF     (256 * SA)          // 9216 floats
#define BTF     (128 * SA)          // 4608 floats
#define STGF    (ATF + BTF)         // 13824 floats
#define SMEM_FUSED (STG * STGF * 4) // 165888 bytes
// gemm3: A 128 + B 128 rows per stage
#define ATF3    (128 * SA)
#define STGF3   (2 * ATF3)
#define SMEM_G3 (STG * STGF3 * 4)   // 110592 bytes
#define EST     133                 // epilogue staging stride (128 rows + 5)

// A tile: 256 rows x KC floats (512 threads -> 4 cpa16 each)
__device__ __forceinline__ void load_tile_A256(uint32_t dst, const float* src, int k0, int t) {
    #pragma unroll
    for (int j = 0; j < 4; j++) {
        int idx = j * 512 + t;
        int row = idx >> 3, seg = idx & 7;
        cpa16(dst + row * (SA * 4) + seg * 16,
              src + (size_t)row * DIM + k0 + seg * 4);
    }
}
// B tile: rows 0..63 = Wg[n0..], rows 64..127 = Wf[n0..] (512 threads -> 2 cpa16 each)
__device__ __forceinline__ void load_tile_B2(uint32_t dst, const float* Wg, const float* Wf,
                                             int n0, int k0, int t) {
    #pragma unroll
    for (int j = 0; j < 2; j++) {
        int idx = j * 512 + t;
        int row = idx >> 3, seg = idx & 7;
        const float* base = (row < 64) ? (Wg + (size_t)(n0 + row) * DIM)
                                       : (Wf + (size_t)(n0 + row - 64) * DIM);
        cpa16(dst + row * (SA * 4) + seg * 16, base + k0 + seg * 4);
    }
}
// 128-row tile (gemm3, 256 threads -> 4 cpa16 each)
__device__ __forceinline__ void load_tile_A(uint32_t dst, const float* src, int k0, int t) {
    #pragma unroll
    for (int j = 0; j < 4; j++) {
        int idx = j * 256 + t;
        int row = idx >> 3, seg = idx & 7;
        cpa16(dst + row * (SA * 4) + seg * 16,
              src + (size_t)row * DIM + k0 + seg * 4);
    }
}

// ====================== fused dual-GEMM + softmax segment-reduce ======================
// grid (8, 512): n0 = bx*64, m0 = by*256. 512 threads, 16 warps.
// Warp tile: M64 x N32 of ONE matrix. wid = wr(0..3) | wmat<<2 | wc<<3.
__global__ __launch_bounds__(512, 1) void gemm_fused(
    const float* __restrict__ bg_, const float* __restrict__ bf_)
{
    extern __shared__ float sm[];
    const uint32_t sb = smem_u32(sm);
    const int t = threadIdx.x;
    const int wid = t >> 5, lid = t & 31;
    const int g = lid >> 2, c = lid & 3;
    const int wr = wid & 3;            // M quarter (64 rows)
    const int wmat = (wid >> 2) & 1;   // 0 = Wg/logits, 1 = Wf/feats
    const int wc = wid >> 3;           // 32-col half

    const int n0 = blockIdx.x * 64;
    const int m0 = blockIdx.y * 256;
    const float* Ab = g_xs + (size_t)m0 * DIM;
    const float* Wg = g_wc[0];
    const float* Wf = g_wc[1];

    float acc[4][4][4];
    #pragma unroll
    for (int mf = 0; mf < 4; mf++)
        #pragma unroll
        for (int nf = 0; nf < 4; nf++)
            #pragma unroll
            for (int q = 0; q < 4; q++) acc[mf][nf][q] = 0.f;

    #pragma unroll
    for (int cc = 0; cc < STG - 1; cc++) {
        load_tile_A256(sb + cc * STGF * 4, Ab, cc * KC, t);
        load_tile_B2(sb + cc * STGF * 4 + ATF * 4, Wg, Wf, n0, cc * KC, t);
        asm volatile("cp.async.commit_group;" ::: "memory");
    }

    for (int i = 0; i < CHUNKS; i++) {
        asm volatile("cp.async.wait_group 1;" ::: "memory");
        __syncthreads();
        int nxt = i + STG - 1;
        if (nxt < CHUNKS) {
            int s = nxt % STG;
            load_tile_A256(sb + s * STGF * 4, Ab, nxt * KC, t);
            load_tile_B2(sb + s * STGF * 4 + ATF * 4, Wg, Wf, n0, nxt * KC, t);
        }
        asm volatile("cp.async.commit_group;" ::: "memory");

        const float* As = sm + (i % STG) * STGF + (wr * 64) * SA;
        const float* Bs = sm + (i % STG) * STGF + ATF + (wmat * 64 + wc * 32) * SA;
        #pragma unroll
        for (int kk = 0; kk < KC; kk += 8) {
            uint32_t a[4][4];
            #pragma unroll
            for (int mf = 0; mf < 4; mf++) {
                const float* ap = As + (mf * 16 + g) * SA + kk + c;
                a[mf][0] = __float_as_uint(ap[0]);
                a[mf][1] = __float_as_uint(ap[8 * SA]);
                a[mf][2] = __float_as_uint(ap[4]);
                a[mf][3] = __float_as_uint(ap[8 * SA + 4]);
            }
            #pragma unroll
            for (int nf = 0; nf < 4; nf++) {
                const float* bp = Bs + (nf * 8 + g) * SA + kk + c;
                uint32_t b0 = __float_as_uint(bp[0]);
                uint32_t b1 = __float_as_uint(bp[4]);
                #pragma unroll
                for (int mf = 0; mf < 4; mf++)
                    mma8(acc[mf][nf], a[mf], b0, b1);
            }
        }
    }
    __syncthreads();

    // ---- epilogue: two passes of 128 rows; stage (l, f) transposed [col][row] ----
    float* sl = sm;
    float* sf = sm + 64 * EST;
    int* sgid = (int*)(sm + 2 * 64 * EST);
    if (t < 256) sgid[t] = g_gids[m0 + t];
    const float* bias = wmat ? bf_ : bg_;
    float* sdst = wmat ? sf : sl;

    #pragma unroll
    for (int p = 0; p < 2; p++) {
        __syncthreads();
        if ((wr >> 1) == p) {
            int rbase = (wr & 1) * 64;   // row offset within this 128-row pass
            #pragma unroll
            for (int nf = 0; nf < 4; nf++) {
                int cb = wc * 32 + nf * 8 + c * 2;
                float2 bv = *(const float2*)(bias + n0 + cb);
                #pragma unroll
                for (int mf = 0; mf < 4; mf++) {
                    int r0 = rbase + mf * 16 + g;
                    sdst[cb * EST + r0]           = acc[mf][nf][0] + bv.x;
                    sdst[(cb + 1) * EST + r0]     = acc[mf][nf][1] + bv.y;
                    sdst[cb * EST + r0 + 8]       = acc[mf][nf][2] + bv.x;
                    sdst[(cb + 1) * EST + r0 + 8] = acc[mf][nf][3] + bv.y;
                }
            }
        }
        __syncthreads();
        // segmented reduce over this pass's 128 sorted rows (512 thr = 64 cols x 8 chunks of 16)
        {
            int col = t & 63, q = t >> 6;
            int gcol = n0 + col;
            int r = q * 16;
            int curg = sgid[p * 128 + r];
            float num = 0.f, den = 0.f;
            #pragma unroll 1
            for (int k = 0; k < 16; k++, r++) {
                int gg = sgid[p * 128 + r];
                float l = sl[col * EST + r];
                float f = sf[col * EST + r];
                float e = __expf(l);
                if (gg != curg) {
                    atomicAdd(&g_num[(size_t)curg * DIM + gcol], num);
                    atomicAdd(&g_den[(size_t)curg * DIM + gcol], den);
                    num = 0.f; den = 0.f; curg = gg;
                }
                num += f * e;
                den += e;
            }
            atomicAdd(&g_num[(size_t)curg * DIM + gcol], num);
            atomicAdd(&g_den[(size_t)curg * DIM + gcol], den);
        }
    }
}

// ====================== GEMM3: out_group = y @ Wh^T + bh ======================
// grid (4, 32), 256 threads, CTA 128x128. Warp tile M32(wr) x N64(wc).
__global__ __launch_bounds__(256, 2) void gemm_mma3(const float* __restrict__ bias)
{
    extern __shared__ float sm[];
    const uint32_t sb = smem_u32(sm);
    const int t = threadIdx.x;
    const int wid = t >> 5, lid = t & 31;
    const int g = lid >> 2, c = lid & 3;
    const int wr = wid & 3, wc = wid >> 2;

    const int m0 = blockIdx.y * 128, n0 = blockIdx.x * 128;
    const float* Ab = g_y + (size_t)m0 * DIM;
    const float* Wb = g_wc[2] + (size_t)n0 * DIM;
    float* C = g_outg;

    float acc[2][8][4];
    #pragma unroll
    for (int mf = 0; mf < 2; mf++)
        #pragma unroll
        for (int nf = 0; nf < 8; nf++)
            #pragma unroll
            for (int q = 0; q < 4; q++) acc[mf][nf][q] = 0.f;

    #pragma unroll
    for (int cc = 0; cc < STG - 1; cc++) {
        load_tile_A(sb + cc * STGF3 * 4,            Ab, cc * KC, t);
        load_tile_A(sb + cc * STGF3 * 4 + ATF3 * 4, Wb, cc * KC, t);
        asm volatile("cp.async.commit_group;" ::: "memory");
    }

    for (int i = 0; i < CHUNKS; i++) {
        asm volatile("cp.async.wait_group 1;" ::: "memory");
        __syncthreads();
        int nxt = i + STG - 1;
        if (nxt < CHUNKS) {
            int s = nxt % STG;
            load_tile_A(sb + s * STGF3 * 4,            Ab, nxt * KC, t);
            load_tile_A(sb + s * STGF3 * 4 + ATF3 * 4, Wb, nxt * KC, t);
        }
        asm volatile("cp.async.commit_group;" ::: "memory");

        const float* As = sm + (i % STG) * STGF3 + (wr * 32) * SA;
        const float* Bs = sm + (i % STG) * STGF3 + ATF3 + (wc * 64) * SA;
        #pragma unroll
        for (int kk = 0; kk < KC; kk += 8) {
            uint32_t a[2][4];
            #pragma unroll
            for (int mf = 0; mf < 2; mf++) {
                const float* ap = As + (mf * 16 + g) * SA + kk + c;
                a[mf][0] = __float_as_uint(ap[0]);
                a[mf][1] = __float_as_uint(ap[8 * SA]);
                a[mf][2] = __float_as_uint(ap[4]);
                a[mf][3] = __float_as_uint(ap[8 * SA + 4]);
            }
            #pragma unroll
            for (int nf = 0; nf < 8; nf++) {
                const float* bp = Bs + (nf * 8 + g) * SA + kk + c;
                uint32_t bb0 = __float_as_uint(bp[0]);
                uint32_t bb1 = __float_as_uint(bp[4]);
                mma8(acc[0][nf], a[0], bb0, bb1);
                mma8(acc[1][nf], a[1], bb0, bb1);
            }
        }
    }

    const int rowb = m0 + wr * 32 + g;
    const int colb = n0 + wc * 64 + c * 2;
    #pragma unroll
    for (int nf = 0; nf < 8; nf++) {
        int col = colb + nf * 8;
        float bv0 = bias[col], bv1 = bias[col + 1];
        #pragma unroll
        for (int mf = 0; mf < 2; mf++) {
            int r0 = rowb + mf * 16;
            float2 v;
            v.x = acc[mf][nf][0] + bv0; v.y = acc[mf][nf][1] + bv1;
            *(float2*)(C + (size_t)r0 * DIM + col) = v;
            v.x = acc[mf][nf][2] + bv0; v.y = acc[mf][nf][3] + bv1;
            *(float2*)(C + (size_t)(r0 + 8) * DIM + col) = v;
        }
    }
}

// ---------------- small kernels ----------------
__global__ void zero_counts_k() {
    int i = blockIdx.x * blockDim.x + threadIdx.x;
    if (i < NGRP) g_counts[i] = 0;
}
__global__ void zero_nd_k() {
    int i = blockIdx.x * blockDim.x + threadIdx.x;
    if (i < NGRP * DIM / 4) {
        float4 z = make_float4(0.f, 0.f, 0.f, 0.f);
        ((float4*)g_num)[i] = z;
        ((float4*)g_den)[i] = z;
    }
}
__global__ void hist_k(const int* __restrict__ jx) {
    int i = blockIdx.x * blockDim.x + threadIdx.x;
    if (i < N_ROWS) atomicAdd(&g_counts[jx[i]], 1);
}
__global__ void scan_k() {
    __shared__ int s[NGRP];
    __shared__ int ps[1024];
    int t = threadIdx.x;
    for (int i = t; i < NGRP; i += 1024) s[i] = g_counts[i];
    __syncthreads();
    int b = t * 4;
    int v0 = s[b], v1 = s[b + 1], v2 = s[b + 2], v3 = s[b + 3];
    int sum = v0 + v1 + v2 + v3;
    ps[t] = sum;
    __syncthreads();
    #pragma unroll
    for (int off = 1; off < 1024; off <<= 1) {
        int x = (t >= off) ? ps[t - off] : 0;
        __syncthreads();
        ps[t] += x;
        __syncthreads();
    }
    int excl = ps[t] - sum;
    int o0 = excl, o1 = o0 + v0, o2 = o1 + v1, o3 = o2 + v2;
    g_offsets[b] = o0;     g_offsets[b + 1] = o1;
    g_offsets[b + 2] = o2; g_offsets[b + 3] = o3;
    g_cursor[b] = o0;      g_cursor[b + 1] = o1;
    g_cursor[b + 2] = o2;  g_cursor[b + 3] = o3;
    if (t == 1023) g_offsets[NGRP] = o3 + v3;
}
__global__ void scatter_k(const int* __restrict__ jx) {
    int i = blockIdx.x * blockDim.x + threadIdx.x;
    if (i < N_ROWS) {
        int g = jx[i];
        int pos = atomicAdd(&g_cursor[g], 1);
        g_perm[pos] = i;
        g_gids[pos] = g;
    }
}

// permuted tf32 convert: g_xs[r] = tf32(x[perm[r]])
__global__ void conv_xs_k(const float4* __restrict__ x) {
    int idx = blockIdx.x * blockDim.x + threadIdx.x;
    if (idx < N_ROWS * (DIM / 4)) {
        int r = idx >> 7, cc = idx & 127;
        int src = g_perm[r];
        float4 v = x[((size_t)src << 7) + cc];
        v.x = tf32r(v.x); v.y = tf32r(v.y); v.z = tf32r(v.z); v.w = tf32r(v.w);
        ((float4*)g_xs)[idx] = v;
    }
}
__global__ void conv_w_k(const float4* __restrict__ Wg, const float4* __restrict__ Wf,
                         const float4* __restrict__ Wh) {
    int i = blockIdx.x * blockDim.x + threadIdx.x;
    const int per = DIM * DIM / 4;
    if (i < 3 * per) {
        int mat = i / per, j = i % per;
        const float4* src = (mat == 0) ? Wg : (mat == 1) ? Wf : Wh;
        float4 v = src[j];
        v.x = tf32r(v.x); v.y = tf32r(v.y); v.z = tf32r(v.z); v.w = tf32r(v.w);
        ((float4*)g_wc[mat])[j] = v;
    }
}

// y = num / (den + eps), tf32-rounded for GEMM3
__global__ void norm_y_k() {
    int i = blockIdx.x * blockDim.x + threadIdx.x;
    if (i < NGRP * DIM) g_y[i] = tf32r(g_num[i] / (g_den[i] + EPSV));
}

// out[i,:] = outg[jx[i],:]
__global__ void gather_k(const int* __restrict__ jx, float4* __restrict__ out) {
    int idx = blockIdx.x * blockDim.x + threadIdx.x;
    if (idx < N_ROWS * (DIM / 4)) {
        int i = idx >> 7;
        int c = idx & 127;
        out[idx] = ((const float4*)g_outg)[((size_t)jx[i] << 7) + c];
    }
}

extern "C" void kernel_launch(void* const* d_in, const int* in_sizes, int n_in,
                              void* d_out, int out_size) {
    const float* x  = (const float*)d_in[0];
    const float* Wf = (const float*)d_in[1];
    const float* bf = (const float*)d_in[2];
    const float* Wg = (const float*)d_in[3];
    const float* bg = (const float*)d_in[4];
    const float* Wh = (const float*)d_in[5];
    const float* bh = (const float*)d_in[6];
    const int*   jx = (const int*)d_in[7];
    float* out = (float*)d_out;
    (void)in_sizes; (void)n_in; (void)out_size;

    cudaFuncSetAttribute(gemm_fused, cudaFuncAttributeMaxDynamicSharedMemorySize, SMEM_FUSED);
    cudaFuncSetAttribute(gemm_mma3,  cudaFuncAttributeMaxDynamicSharedMemorySize, SMEM_G3);

    // zero accumulators + counting sort of jx
    zero_counts_k<<<(NGRP + 255) / 256, 256>>>();
    zero_nd_k<<<(NGRP * DIM / 4 + 255) / 256, 256>>>();
    hist_k<<<(N_ROWS + 255) / 256, 256>>>(jx);
    scan_k<<<1, 1024>>>();
    scatter_k<<<(N_ROWS + 255) / 256, 256>>>(jx);

    // tf32 pre-conversion (x permuted into sorted order)
    conv_w_k<<<(3 * DIM * DIM / 4 + 255) / 256, 256>>>(
        (const float4*)Wg, (const float4*)Wf, (const float4*)Wh);
    conv_xs_k<<<(N_ROWS * (DIM / 4) + 255) / 256, 256>>>((const float4*)x);

    // fused dual GEMM + softmax segment-reduce (M256 x N64x2 tiles)
    gemm_fused<<<dim3(8, N_ROWS / 256), 512, SMEM_FUSED>>>(bg, bf);

    // y = num/(den+eps)
    norm_y_k<<<(NGRP * DIM + 255) / 256, 256>>>();

    // out_group = y @ Wh^T + bh
    gemm_mma3<<<dim3(4, NGRP / 128), 256, SMEM_G3>>>(bh);

    // out = out_group[jx]
    gather_k<<<(N_ROWS * (DIM / 4) + 255) / 256, 256>>>(jx, (float4*)out);
}

// round 12
// speedup vs baseline: 1.2723x; 1.1799x over previous
#include <cuda_runtime.h>
#include <math.h>
#include <stdint.h>

#define N_ROWS 131072
#define DIM    512
#define NGRP   4096
#define EPSV   1e-12f

// ---------------- scratch (static device arrays; no allocation allowed) ----------------
__device__ float g_wc    [3][DIM * DIM];           // tf32-rounded Wg*(1+2^-11), Wf*(1+2^-11), Wh
__device__ float g_num   [NGRP * DIM];             // segment sums: feats*exp(l)
__device__ float g_den   [NGRP * DIM];             // segment sums: exp(l)
__device__ float g_y     [NGRP * DIM];             // normalized aggregate (tf32-rounded)
__device__ float g_outg  [NGRP * DIM];
__device__ int   g_counts [NGRP];
__device__ int   g_offsets[NGRP + 1];
__device__ int   g_cursor [NGRP];
__device__ int   g_perm   [N_ROWS];
__device__ int   g_gids   [N_ROWS];                // sorted group id per sorted row

// RZ-truncation compensation for un-prerounded A operand: E[trunc] = a*(1-2^-11)
#define COMP 1.00048828125f

// ====================== helpers ======================
__device__ __forceinline__ uint32_t smem_u32(const void* p) {
    uint32_t a;
    asm("{ .reg .u64 t; cvta.to.shared.u64 t, %1; cvt.u32.u64 %0, t; }" : "=r"(a) : "l"(p));
    return a;
}
__device__ __forceinline__ void cpa16(uint32_t dst, const void* src) {
    asm volatile("cp.async.cg.shared.global [%0], [%1], 16;" :: "r"(dst), "l"(src) : "memory");
}
__device__ __forceinline__ float tf32r(float x) {
    uint32_t u;
    asm("cvt.rna.tf32.f32 %0, %1;" : "=r"(u) : "f"(x));
    return __uint_as_float(u);
}
__device__ __forceinline__ void mma8(float* d, const uint32_t* a, uint32_t b0, uint32_t b1) {
    asm volatile(
        "mma.sync.aligned.m16n8k8.row.col.f32.tf32.tf32.f32 "
        "{%0,%1,%2,%3}, {%4,%5,%6,%7}, {%8,%9}, {%0,%1,%2,%3};"
        : "+f"(d[0]), "+f"(d[1]), "+f"(d[2]), "+f"(d[3])
        : "r"(a[0]), "r"(a[1]), "r"(a[2]), "r"(a[3]), "r"(b0), "r"(b1));
}

// ====================== GEMM tiling constants ======================
#define KC      32
#define CHUNKS  (DIM / KC)          // 16
#define STG     3
#define SA      36                  // floats per smem row (KC + 4 pad)
#define ATF     (128 * SA)
#define STGF    (2 * ATF)           // A 128 rows + B 128 rows
#define SMEM_MAIN (STG * STGF * 4)  // 110592 bytes
#define SMEM_B    (SMEM_MAIN + 512) // + perm slice (128 ints)
#define EST     133                 // epilogue staging stride

// 128 rows x KC floats, contiguous rows
__device__ __forceinline__ void load_tile_A(uint32_t dst, const float* src, int k0, int t) {
    #pragma unroll
    for (int j = 0; j < 4; j++) {
        int idx = j * 256 + t;
        int row = idx >> 3, seg = idx & 7;
        cpa16(dst + row * (SA * 4) + seg * 16,
              src + (size_t)row * DIM + k0 + seg * 4);
    }
}
// 128 rows x KC floats, rows indirected through smem perm table
__device__ __forceinline__ void load_tile_Aperm(uint32_t dst, const float* src,
                                                const int* perm_s, int k0, int t) {
    #pragma unroll
    for (int j = 0; j < 4; j++) {
        int idx = j * 256 + t;
        int row = idx >> 3, seg = idx & 7;
        cpa16(dst + row * (SA * 4) + seg * 16,
              src + (size_t)perm_s[row] * DIM + k0 + seg * 4);
    }
}
// B tile: rows 0..63 = Wg[n0..], rows 64..127 = Wf[n0..]
__device__ __forceinline__ void load_tile_B2(uint32_t dst, const float* Wg, const float* Wf,
                                             int n0, int k0, int t) {
    #pragma unroll
    for (int j = 0; j < 4; j++) {
        int idx = j * 256 + t;
        int row = idx >> 3, seg = idx & 7;
        const float* base = (row < 64) ? (Wg + (size_t)(n0 + row) * DIM)
                                       : (Wf + (size_t)(n0 + row - 64) * DIM);
        cpa16(dst + row * (SA * 4) + seg * 16, base + k0 + seg * 4);
    }
}

// ====================== fused dual-GEMM + softmax segment-reduce ======================
// grid (8, 1024): n0 = bx*64, m0 = by*128. A = x (raw fp32), rows via perm table.
__global__ __launch_bounds__(256, 2) void gemm_fused(
    const float* __restrict__ x_, const float* __restrict__ bg_, const float* __restrict__ bf_)
{
    extern __shared__ float sm[];
    const uint32_t sb = smem_u32(sm);
    int* perm_s = (int*)(sm + STG * STGF);
    const int t = threadIdx.x;
    const int wid = t >> 5, lid = t & 31;
    const int g = lid >> 2, c = lid & 3;
    const int wr = wid & 3, wc = wid >> 2;

    const int n0 = blockIdx.x * 64;
    const int m0 = blockIdx.y * 128;
    const float* Wg = g_wc[0];
    const float* Wf = g_wc[1];

    if (t < 128) perm_s[t] = g_perm[m0 + t];
    __syncthreads();

    float accg[2][4][4], accf[2][4][4];
    #pragma unroll
    for (int mf = 0; mf < 2; mf++)
        #pragma unroll
        for (int nf = 0; nf < 4; nf++)
            #pragma unroll
            for (int q = 0; q < 4; q++) { accg[mf][nf][q] = 0.f; accf[mf][nf][q] = 0.f; }

    #pragma unroll
    for (int cc = 0; cc < STG - 1; cc++) {
        load_tile_Aperm(sb + cc * STGF * 4, x_, perm_s, cc * KC, t);
        load_tile_B2(sb + cc * STGF * 4 + ATF * 4, Wg, Wf, n0, cc * KC, t);
        asm volatile("cp.async.commit_group;" ::: "memory");
    }

    for (int i = 0; i < CHUNKS; i++) {
        asm volatile("cp.async.wait_group 1;" ::: "memory");
        __syncthreads();
        int nxt = i + STG - 1;
        if (nxt < CHUNKS) {
            int s = nxt % STG;
            load_tile_Aperm(sb + s * STGF * 4, x_, perm_s, nxt * KC, t);
            load_tile_B2(sb + s * STGF * 4 + ATF * 4, Wg, Wf, n0, nxt * KC, t);
        }
        asm volatile("cp.async.commit_group;" ::: "memory");

        const float* As = sm + (i % STG) * STGF + (wr * 32) * SA;
        const float* B0 = sm + (i % STG) * STGF + ATF + (wc * 32) * SA;
        #pragma unroll
        for (int kk = 0; kk < KC; kk += 8) {
            uint32_t a[2][4];
            #pragma unroll
            for (int mf = 0; mf < 2; mf++) {
                const float* ap = As + (mf * 16 + g) * SA + kk + c;
                a[mf][0] = __float_as_uint(ap[0]);
                a[mf][1] = __float_as_uint(ap[8 * SA]);
                a[mf][2] = __float_as_uint(ap[4]);
                a[mf][3] = __float_as_uint(ap[8 * SA + 4]);
            }
            #pragma unroll
            for (int nf = 0; nf < 4; nf++) {
                const float* bp0 = B0 + (nf * 8 + g) * SA + kk + c;
                uint32_t p0 = __float_as_uint(bp0[0]);
                uint32_t p1 = __float_as_uint(bp0[4]);
                mma8(accg[0][nf], a[0], p0, p1);
                mma8(accg[1][nf], a[1], p0, p1);
                const float* bp1 = bp0 + 64 * SA;
                uint32_t q0 = __float_as_uint(bp1[0]);
                uint32_t q1 = __float_as_uint(bp1[4]);
                mma8(accf[0][nf], a[0], q0, q1);
                mma8(accf[1][nf], a[1], q0, q1);
            }
        }
    }
    __syncthreads();

    // ---- epilogue: stage (l, f) transposed [col][row], stride EST ----
    float* sl = sm;
    float* sf = sm + 64 * EST;
    int* sgid = (int*)(sm + 2 * 64 * EST);
    if (t < 128) sgid[t] = g_gids[m0 + t];
    #pragma unroll
    for (int nf = 0; nf < 4; nf++) {
        int cb = wc * 32 + nf * 8 + c * 2;
        float2 bgv = *(const float2*)(bg_ + n0 + cb);
        float2 bfv = *(const float2*)(bf_ + n0 + cb);
        #pragma unroll
        for (int mf = 0; mf < 2; mf++) {
            int r0 = wr * 32 + mf * 16 + g;
            sl[cb * EST + r0]           = accg[mf][nf][0] + bgv.x;
            sl[(cb + 1) * EST + r0]     = accg[mf][nf][1] + bgv.y;
            sl[cb * EST + r0 + 8]       = accg[mf][nf][2] + bgv.x;
            sl[(cb + 1) * EST + r0 + 8] = accg[mf][nf][3] + bgv.y;
            sf[cb * EST + r0]           = accf[mf][nf][0] + bfv.x;
            sf[(cb + 1) * EST + r0]     = accf[mf][nf][1] + bfv.y;
            sf[cb * EST + r0 + 8]       = accf[mf][nf][2] + bfv.x;
            sf[(cb + 1) * EST + r0 + 8] = accf[mf][nf][3] + bfv.y;
        }
    }
    __syncthreads();

    // ---- segmented reduce over sorted rows; flush per group via atomics ----
    {
        int col = t & 63, q = t >> 6;
        int gcol = n0 + col;
        int r = q * 32;
        int curg = sgid[r];
        float num = 0.f, den = 0.f;
        #pragma unroll 1
        for (int k = 0; k < 32; k++, r++) {
            int gg = sgid[r];
            float l = sl[col * EST + r];
            float f = sf[col * EST + r];
            float e = __expf(l);
            if (gg != curg) {
                atomicAdd(&g_num[(size_t)curg * DIM + gcol], num);
                atomicAdd(&g_den[(size_t)curg * DIM + gcol], den);
                num = 0.f; den = 0.f; curg = gg;
            }
            num += f * e;
            den += e;
        }
        atomicAdd(&g_num[(size_t)curg * DIM + gcol], num);
        atomicAdd(&g_den[(size_t)curg * DIM + gcol], den);
    }
}

// ====================== GEMM3: out_group = y @ Wh^T + bh ======================
// grid (4, 32), CTA 128x128
__global__ __launch_bounds__(256, 2) void gemm_mma3(const float* __restrict__ bias)
{
    extern __shared__ float sm[];
    const uint32_t sb = smem_u32(sm);
    const int t = threadIdx.x;
    const int wid = t >> 5, lid = t & 31;
    const int g = lid >> 2, c = lid & 3;
    const int wr = wid & 3, wc = wid >> 2;

    const int m0 = blockIdx.y * 128, n0 = blockIdx.x * 128;
    const float* Ab = g_y + (size_t)m0 * DIM;
    const float* Wb = g_wc[2] + (size_t)n0 * DIM;
    float* C = g_outg;

    float acc[2][8][4];
    #pragma unroll
    for (int mf = 0; mf < 2; mf++)
        #pragma unroll
        for (int nf = 0; nf < 8; nf++)
            #pragma unroll
            for (int q = 0; q < 4; q++) acc[mf][nf][q] = 0.f;

    #pragma unroll
    for (int cc = 0; cc < STG - 1; cc++) {
        load_tile_A(sb + cc * STGF * 4,           Ab, cc * KC, t);
        load_tile_A(sb + cc * STGF * 4 + ATF * 4, Wb, cc * KC, t);
        asm volatile("cp.async.commit_group;" ::: "memory");
    }

    for (int i = 0; i < CHUNKS; i++) {
        asm volatile("cp.async.wait_group 1;" ::: "memory");
        __syncthreads();
        int nxt = i + STG - 1;
        if (nxt < CHUNKS) {
            int s = nxt % STG;
            load_tile_A(sb + s * STGF * 4,           Ab, nxt * KC, t);
            load_tile_A(sb + s * STGF * 4 + ATF * 4, Wb, nxt * KC, t);
        }
        asm volatile("cp.async.commit_group;" ::: "memory");

        const float* As = sm + (i % STG) * STGF + (wr * 32) * SA;
        const float* Bs = sm + (i % STG) * STGF + ATF + (wc * 64) * SA;
        #pragma unroll
        for (int kk = 0; kk < KC; kk += 8) {
            uint32_t a[2][4];
            #pragma unroll
            for (int mf = 0; mf < 2; mf++) {
                const float* ap = As + (mf * 16 + g) * SA + kk + c;
                a[mf][0] = __float_as_uint(ap[0]);
                a[mf][1] = __float_as_uint(ap[8 * SA]);
                a[mf][2] = __float_as_uint(ap[4]);
                a[mf][3] = __float_as_uint(ap[8 * SA + 4]);
            }
            #pragma unroll
            for (int nf = 0; nf < 8; nf++) {
                const float* bp = Bs + (nf * 8 + g) * SA + kk + c;
                uint32_t bb0 = __float_as_uint(bp[0]);
                uint32_t bb1 = __float_as_uint(bp[4]);
                mma8(acc[0][nf], a[0], bb0, bb1);
                mma8(acc[1][nf], a[1], bb0, bb1);
            }
        }
    }

    const int rowb = m0 + wr * 32 + g;
    const int colb = n0 + wc * 64 + c * 2;
    #pragma unroll
    for (int nf = 0; nf < 8; nf++) {
        int col = colb + nf * 8;
        float bv0 = bias[col], bv1 = bias[col + 1];
        #pragma unroll
        for (int mf = 0; mf < 2; mf++) {
            int r0 = rowb + mf * 16;
            float2 v;
            v.x = acc[mf][nf][0] + bv0; v.y = acc[mf][nf][1] + bv1;
            *(float2*)(C + (size_t)r0 * DIM + col) = v;
            v.x = acc[mf][nf][2] + bv0; v.y = acc[mf][nf][3] + bv1;
            *(float2*)(C + (size_t)(r0 + 8) * DIM + col) = v;
        }
    }
}

// ---------------- small kernels ----------------
__global__ void zero_counts_k() {
    int i = blockIdx.x * blockDim.x + threadIdx.x;
    if (i < NGRP) g_counts[i] = 0;
}
__global__ void zero_nd_k() {
    int i = blockIdx.x * blockDim.x + threadIdx.x;
    if (i < NGRP * DIM / 4) {
        float4 z = make_float4(0.f, 0.f, 0.f, 0.f);
        ((float4*)g_num)[i] = z;
        ((float4*)g_den)[i] = z;
    }
}
__global__ void hist_k(const int* __restrict__ jx) {
    int i = blockIdx.x * blockDim.x + threadIdx.x;
    if (i < N_ROWS) atomicAdd(&g_counts[jx[i]], 1);
}
__global__ void scan_k() {
    __shared__ int s[NGRP];
    __shared__ int ps[1024];
    int t = threadIdx.x;
    for (int i = t; i < NGRP; i += 1024) s[i] = g_counts[i];
    __syncthreads();
    int b = t * 4;
    int v0 = s[b], v1 = s[b + 1], v2 = s[b + 2], v3 = s[b + 3];
    int sum = v0 + v1 + v2 + v3;
    ps[t] = sum;
    __syncthreads();
    #pragma unroll
    for (int off = 1; off < 1024; off <<= 1) {
        int x = (t >= off) ? ps[t - off] : 0;
        __syncthreads();
        ps[t] += x;
        __syncthreads();
    }
    int excl = ps[t] - sum;
    int o0 = excl, o1 = o0 + v0, o2 = o1 + v1, o3 = o2 + v2;
    g_offsets[b] = o0;     g_offsets[b + 1] = o1;
    g_offsets[b + 2] = o2; g_offsets[b + 3] = o3;
    g_cursor[b] = o0;      g_cursor[b + 1] = o1;
    g_cursor[b + 2] = o2;  g_cursor[b + 3] = o3;
    if (t == 1023) g_offsets[NGRP] = o3 + v3;
}
__global__ void scatter_k(const int* __restrict__ jx) {
    int i = blockIdx.x * blockDim.x + threadIdx.x;
    if (i < N_ROWS) {
        int g = jx[i];
        int pos = atomicAdd(&g_cursor[g], 1);
        g_perm[pos] = i;
        g_gids[pos] = g;
    }
}

// W conversion: Wg/Wf scaled by COMP (RZ-bias compensation) then RNA-rounded; Wh plain RNA
__global__ void conv_w_k(const float4* __restrict__ Wg, const float4* __restrict__ Wf,
                         const float4* __restrict__ Wh) {
    int i = blockIdx.x * blockDim.x + threadIdx.x;
    const int per = DIM * DIM / 4;
    if (i < 3 * per) {
        int mat = i / per, j = i % per;
        const float4* src = (mat == 0) ? Wg : (mat == 1) ? Wf : Wh;
        float s = (mat == 2) ? 1.0f : COMP;
        float4 v = src[j];
        v.x = tf32r(v.x * s); v.y = tf32r(v.y * s);
        v.z = tf32r(v.z * s); v.w = tf32r(v.w * s);
        ((float4*)g_wc[mat])[j] = v;
    }
}

// y = num / (den + eps), tf32-rounded for GEMM3
__global__ void norm_y_k() {
    int i = blockIdx.x * blockDim.x + threadIdx.x;
    if (i < NGRP * DIM) g_y[i] = tf32r(g_num[i] / (g_den[i] + EPSV));
}

// out[i,:] = outg[jx[i],:]
__global__ void gather_k(const int* __restrict__ jx, float4* __restrict__ out) {
    int idx = blockIdx.x * blockDim.x + threadIdx.x;
    if (idx < N_ROWS * (DIM / 4)) {
        int i = idx >> 7;
        int c = idx & 127;
        out[idx] = ((const float4*)g_outg)[((size_t)jx[i] << 7) + c];
    }
}

extern "C" void kernel_launch(void* const* d_in, const int* in_sizes, int n_in,
                              void* d_out, int out_size) {
    const float* x  = (const float*)d_in[0];
    const float* Wf = (const float*)d_in[1];
    const float* bf = (const float*)d_in[2];
    const float* Wg = (const float*)d_in[3];
    const float* bg = (const float*)d_in[4];
    const float* Wh = (const float*)d_in[5];
    const float* bh = (const float*)d_in[6];
    const int*   jx = (const int*)d_in[7];
    float* out = (float*)d_out;
    (void)in_sizes; (void)n_in; (void)out_size;

    cudaFuncSetAttribute(gemm_fused, cudaFuncAttributeMaxDynamicSharedMemorySize, SMEM_B);
    cudaFuncSetAttribute(gemm_mma3,  cudaFuncAttributeMaxDynamicSharedMemorySize, SMEM_MAIN);

    // zero accumulators + counting sort of jx
    zero_counts_k<<<(NGRP + 255) / 256, 256>>>();
    zero_nd_k<<<(NGRP * DIM / 4 + 255) / 256, 256>>>();
    hist_k<<<(N_ROWS + 255) / 256, 256>>>(jx);
    scan_k<<<1, 1024>>>();
    scatter_k<<<(N_ROWS + 255) / 256, 256>>>(jx);

    // W pre-conversion only (x is consumed raw, RZ-truncated by the mma, bias-compensated in W)
    conv_w_k<<<(3 * DIM * DIM / 4 + 255) / 256, 256>>>(
        (const float4*)Wg, (const float4*)Wf, (const float4*)Wh);

    // fused dual GEMM + softmax segment-reduce
    gemm_fused<<<dim3(8, N_ROWS / 128), 256, SMEM_B>>>(x, bg, bf);

    // y = num/(den+eps)
    norm_y_k<<<(NGRP * DIM + 255) / 256, 256>>>();

    // out_group = y @ Wh^T + bh
    gemm_mma3<<<dim3(4, NGRP / 128), 256, SMEM_MAIN>>>(bh);

    // out = out_group[jx]
    gather_k<<<(N_ROWS * (DIM / 4) + 255) / 256, 256>>>(jx, (float4*)out);
}

// round 13
// speedup vs baseline: 1.3092x; 1.0290x over previous
#include <cuda_runtime.h>
#include <math.h>
#include <stdint.h>

#define N_ROWS 131072
#define DIM    512
#define NGRP   4096
#define EPSV   1e-12f

// ---------------- scratch (static device arrays; no allocation allowed) ----------------
__device__ float g_wc    [3][DIM * DIM];           // tf32-rounded Wg*(1+2^-11), Wf*(1+2^-11), Wh
__device__ float g_num   [NGRP * DIM];             // segment sums: feats*exp(l)
__device__ float g_den   [NGRP * DIM];             // segment sums: exp(l)
__device__ float g_y     [NGRP * DIM];             // normalized aggregate (tf32-rounded)
__device__ float g_outg  [NGRP * DIM];
__device__ int   g_counts [NGRP];
__device__ int   g_offsets[NGRP + 1];
__device__ int   g_cursor [NGRP];
__device__ int   g_perm   [N_ROWS];
__device__ int   g_gids   [N_ROWS];                // sorted group id per sorted row

// RZ-truncation compensation for un-prerounded A operand: E[trunc] = a*(1-2^-11)
#define COMP 1.00048828125f

// ====================== helpers ======================
__device__ __forceinline__ uint32_t smem_u32(const void* p) {
    uint32_t a;
    asm("{ .reg .u64 t; cvta.to.shared.u64 t, %1; cvt.u32.u64 %0, t; }" : "=r"(a) : "l"(p));
    return a;
}
__device__ __forceinline__ void cpa16(uint32_t dst, const void* src) {
    asm volatile("cp.async.cg.shared.global [%0], [%1], 16;" :: "r"(dst), "l"(src) : "memory");
}
__device__ __forceinline__ float tf32r(float x) {
    uint32_t u;
    asm("cvt.rna.tf32.f32 %0, %1;" : "=r"(u) : "f"(x));
    return __uint_as_float(u);
}
__device__ __forceinline__ void mma8(float* d, const uint32_t* a, uint32_t b0, uint32_t b1) {
    asm volatile(
        "mma.sync.aligned.m16n8k8.row.col.f32.tf32.tf32.f32 "
        "{%0,%1,%2,%3}, {%4,%5,%6,%7}, {%8,%9}, {%0,%1,%2,%3};"
        : "+f"(d[0]), "+f"(d[1]), "+f"(d[2]), "+f"(d[3])
        : "r"(a[0]), "r"(a[1]), "r"(a[2]), "r"(a[3]), "r"(b0), "r"(b1));
}

// ====================== GEMM tiling constants ======================
#define KC      32
#define CHUNKS  (DIM / KC)          // 16
#define STG     3
#define SA      36                  // floats per smem row (KC + 4 pad)
#define ATF     (128 * SA)
#define STGF    (2 * ATF)           // A 128 rows + B 128 rows
#define SMEM_MAIN (STG * STGF * 4)  // 110592 bytes
#define SMEM_B    (SMEM_MAIN + 512) // + perm slice (128 ints)
#define EST     133                 // epilogue staging stride

// 128 rows x KC floats, contiguous rows (256 threads)
__device__ __forceinline__ void load_tile_A(uint32_t dst, const float* src, int k0, int t) {
    #pragma unroll
    for (int j = 0; j < 4; j++) {
        int idx = j * 256 + t;
        int row = idx >> 3, seg = idx & 7;
        cpa16(dst + row * (SA * 4) + seg * 16,
              src + (size_t)row * DIM + k0 + seg * 4);
    }
}
// 128 rows x KC floats, rows indirected through smem perm table (128 threads)
__device__ __forceinline__ void load_tile_Aperm128(uint32_t dst, const float* src,
                                                   const int* perm_s, int k0, int t) {
    #pragma unroll
    for (int j = 0; j < 8; j++) {
        int idx = j * 128 + t;
        int row = idx >> 3, seg = idx & 7;
        cpa16(dst + row * (SA * 4) + seg * 16,
              src + (size_t)perm_s[row] * DIM + k0 + seg * 4);
    }
}
// B tile: rows 0..63 = Wg[n0..], rows 64..127 = Wf[n0..] (128 threads)
__device__ __forceinline__ void load_tile_B2_128(uint32_t dst, const float* Wg, const float* Wf,
                                                 int n0, int k0, int t) {
    #pragma unroll
    for (int j = 0; j < 8; j++) {
        int idx = j * 128 + t;
        int row = idx >> 3, seg = idx & 7;
        const float* base = (row < 64) ? (Wg + (size_t)(n0 + row) * DIM)
                                       : (Wf + (size_t)(n0 + row - 64) * DIM);
        cpa16(dst + row * (SA * 4) + seg * 16, base + k0 + seg * 4);
    }
}

// ====================== fused dual-GEMM + softmax segment-reduce ======================
// grid (8, 1024): n0 = bx*64, m0 = by*128. A = x (raw fp32), rows via perm table.
// 128 threads, 4 warps. Warp tile: M64(wr) x N64 of ONE matrix (wmat).
__global__ __launch_bounds__(128, 2) void gemm_fused(
    const float* __restrict__ x_, const float* __restrict__ bg_, const float* __restrict__ bf_)
{
    extern __shared__ float sm[];
    const uint32_t sb = smem_u32(sm);
    int* perm_s = (int*)(sm + STG * STGF);
    const int t = threadIdx.x;
    const int wid = t >> 5, lid = t & 31;
    const int g = lid >> 2, c = lid & 3;
    const int wr = wid & 1;            // M half (64 rows)
    const int wmat = wid >> 1;         // 0 = Wg/logits, 1 = Wf/feats

    const int n0 = blockIdx.x * 64;
    const int m0 = blockIdx.y * 128;
    const float* Wg = g_wc[0];
    const float* Wf = g_wc[1];

    perm_s[t] = g_perm[m0 + t];
    __syncthreads();

    float acc[4][8][4];
    #pragma unroll
    for (int mf = 0; mf < 4; mf++)
        #pragma unroll
        for (int nf = 0; nf < 8; nf++)
            #pragma unroll
            for (int q = 0; q < 4; q++) acc[mf][nf][q] = 0.f;

    #pragma unroll
    for (int cc = 0; cc < STG - 1; cc++) {
        load_tile_Aperm128(sb + cc * STGF * 4, x_, perm_s, cc * KC, t);
        load_tile_B2_128(sb + cc * STGF * 4 + ATF * 4, Wg, Wf, n0, cc * KC, t);
        asm volatile("cp.async.commit_group;" ::: "memory");
    }

    for (int i = 0; i < CHUNKS; i++) {
        asm volatile("cp.async.wait_group 1;" ::: "memory");
        __syncthreads();
        int nxt = i + STG - 1;
        if (nxt < CHUNKS) {
            int s = nxt % STG;
            load_tile_Aperm128(sb + s * STGF * 4, x_, perm_s, nxt * KC, t);
            load_tile_B2_128(sb + s * STGF * 4 + ATF * 4, Wg, Wf, n0, nxt * KC, t);
        }
        asm volatile("cp.async.commit_group;" ::: "memory");

        const float* As = sm + (i % STG) * STGF + (wr * 64) * SA;
        const float* Bs = sm + (i % STG) * STGF + ATF + (wmat * 64) * SA;
        #pragma unroll
        for (int kk = 0; kk < KC; kk += 8) {
            uint32_t a[4][4];
            #pragma unroll
            for (int mf = 0; mf < 4; mf++) {
                const float* ap = As + (mf * 16 + g) * SA + kk + c;
                a[mf][0] = __float_as_uint(ap[0]);
                a[mf][1] = __float_as_uint(ap[8 * SA]);
                a[mf][2] = __float_as_uint(ap[4]);
                a[mf][3] = __float_as_uint(ap[8 * SA + 4]);
            }
            #pragma unroll
            for (int nf = 0; nf < 8; nf++) {
                const float* bp = Bs + (nf * 8 + g) * SA + kk + c;
                uint32_t b0 = __float_as_uint(bp[0]);
                uint32_t b1 = __float_as_uint(bp[4]);
                #pragma unroll
                for (int mf = 0; mf < 4; mf++)
                    mma8(acc[mf][nf], a[mf], b0, b1);
            }
        }
    }
    __syncthreads();

    // ---- epilogue: stage (l, f) transposed [col][row], stride EST ----
    float* sl = sm;
    float* sf = sm + 64 * EST;
    int* sgid = (int*)(sm + 2 * 64 * EST);
    sgid[t] = g_gids[m0 + t];
    float* sdst = wmat ? sf : sl;
    const float* bias = wmat ? bf_ : bg_;
    #pragma unroll
    for (int nf = 0; nf < 8; nf++) {
        int cb = nf * 8 + c * 2;
        float2 bv = *(const float2*)(bias + n0 + cb);
        #pragma unroll
        for (int mf = 0; mf < 4; mf++) {
            int r0 = wr * 64 + mf * 16 + g;
            sdst[cb * EST + r0]           = acc[mf][nf][0] + bv.x;
            sdst[(cb + 1) * EST + r0]     = acc[mf][nf][1] + bv.y;
            sdst[cb * EST + r0 + 8]       = acc[mf][nf][2] + bv.x;
            sdst[(cb + 1) * EST + r0 + 8] = acc[mf][nf][3] + bv.y;
        }
    }
    __syncthreads();

    // ---- segmented reduce over sorted rows; flush per group via atomics ----
    // 128 threads = 64 cols x 2 chunks of 64 rows
    {
        int col = t & 63, q = t >> 6;
        int gcol = n0 + col;
        int r = q * 64;
        int curg = sgid[r];
        float num = 0.f, den = 0.f;
        #pragma unroll 1
        for (int k = 0; k < 64; k++, r++) {
            int gg = sgid[r];
            float l = sl[col * EST + r];
            float f = sf[col * EST + r];
            float e = __expf(l);
            if (gg != curg) {
                atomicAdd(&g_num[(size_t)curg * DIM + gcol], num);
                atomicAdd(&g_den[(size_t)curg * DIM + gcol], den);
                num = 0.f; den = 0.f; curg = gg;
            }
            num += f * e;
            den += e;
        }
        atomicAdd(&g_num[(size_t)curg * DIM + gcol], num);
        atomicAdd(&g_den[(size_t)curg * DIM + gcol], den);
    }
}

// ====================== GEMM3: out_group = y @ Wh^T + bh ======================
// grid (4, 32), 256 threads, CTA 128x128
__global__ __launch_bounds__(256, 2) void gemm_mma3(const float* __restrict__ bias)
{
    extern __shared__ float sm[];
    const uint32_t sb = smem_u32(sm);
    const int t = threadIdx.x;
    const int wid = t >> 5, lid = t & 31;
    const int g = lid >> 2, c = lid & 3;
    const int wr = wid & 3, wc = wid >> 2;

    const int m0 = blockIdx.y * 128, n0 = blockIdx.x * 128;
    const float* Ab = g_y + (size_t)m0 * DIM;
    const float* Wb = g_wc[2] + (size_t)n0 * DIM;
    float* C = g_outg;

    float acc[2][8][4];
    #pragma unroll
    for (int mf = 0; mf < 2; mf++)
        #pragma unroll
        for (int nf = 0; nf < 8; nf++)
            #pragma unroll
            for (int q = 0; q < 4; q++) acc[mf][nf][q] = 0.f;

    #pragma unroll
    for (int cc = 0; cc < STG - 1; cc++) {
        load_tile_A(sb + cc * STGF * 4,           Ab, cc * KC, t);
        load_tile_A(sb + cc * STGF * 4 + ATF * 4, Wb, cc * KC, t);
        asm volatile("cp.async.commit_group;" ::: "memory");
    }

    for (int i = 0; i < CHUNKS; i++) {
        asm volatile("cp.async.wait_group 1;" ::: "memory");
        __syncthreads();
        int nxt = i + STG - 1;
        if (nxt < CHUNKS) {
            int s = nxt % STG;
            load_tile_A(sb + s * STGF * 4,           Ab, nxt * KC, t);
            load_tile_A(sb + s * STGF * 4 + ATF * 4, Wb, nxt * KC, t);
        }
        asm volatile("cp.async.commit_group;" ::: "memory");

        const float* As = sm + (i % STG) * STGF + (wr * 32) * SA;
        const float* Bs = sm + (i % STG) * STGF + ATF + (wc * 64) * SA;
        #pragma unroll
        for (int kk = 0; kk < KC; kk += 8) {
            uint32_t a[2][4];
            #pragma unroll
            for (int mf = 0; mf < 2; mf++) {
                const float* ap = As + (mf * 16 + g) * SA + kk + c;
                a[mf][0] = __float_as_uint(ap[0]);
                a[mf][1] = __float_as_uint(ap[8 * SA]);
                a[mf][2] = __float_as_uint(ap[4]);
                a[mf][3] = __float_as_uint(ap[8 * SA + 4]);
            }
            #pragma unroll
            for (int nf = 0; nf < 8; nf++) {
                const float* bp = Bs + (nf * 8 + g) * SA + kk + c;
                uint32_t bb0 = __float_as_uint(bp[0]);
                uint32_t bb1 = __float_as_uint(bp[4]);
                mma8(acc[0][nf], a[0], bb0, bb1);
                mma8(acc[1][nf], a[1], bb0, bb1);
            }
        }
    }

    const int rowb = m0 + wr * 32 + g;
    const int colb = n0 + wc * 64 + c * 2;
    #pragma unroll
    for (int nf = 0; nf < 8; nf++) {
        int col = colb + nf * 8;
        float bv0 = bias[col], bv1 = bias[col + 1];
        #pragma unroll
        for (int mf = 0; mf < 2; mf++) {
            int r0 = rowb + mf * 16;
            float2 v;
            v.x = acc[mf][nf][0] + bv0; v.y = acc[mf][nf][1] + bv1;
            *(float2*)(C + (size_t)r0 * DIM + col) = v;
            v.x = acc[mf][nf][2] + bv0; v.y = acc[mf][nf][3] + bv1;
            *(float2*)(C + (size_t)(r0 + 8) * DIM + col) = v;
        }
    }
}

// ---------------- small kernels ----------------
__global__ void zero_nd_k() {
    int i = blockIdx.x * blockDim.x + threadIdx.x;
    if (i < NGRP * DIM / 4) {
        float4 z = make_float4(0.f, 0.f, 0.f, 0.f);
        ((float4*)g_num)[i] = z;
        ((float4*)g_den)[i] = z;
    }
    if (i < NGRP) g_counts[i] = 0;
}
__global__ void hist_k(const int* __restrict__ jx) {
    int i = blockIdx.x * blockDim.x + threadIdx.x;
    if (i < N_ROWS) atomicAdd(&g_counts[jx[i]], 1);
}
__global__ void scan_k() {
    __shared__ int s[NGRP];
    __shared__ int ps[1024];
    int t = threadIdx.x;
    for (int i = t; i < NGRP; i += 1024) s[i] = g_counts[i];
    __syncthreads();
    int b = t * 4;
    int v0 = s[b], v1 = s[b + 1], v2 = s[b + 2], v3 = s[b + 3];
    int sum = v0 + v1 + v2 + v3;
    ps[t] = sum;
    __syncthreads();
    #pragma unroll
    for (int off = 1; off < 1024; off <<= 1) {
        int x = (t >= off) ? ps[t - off] : 0;
        __syncthreads();
        ps[t] += x;
        __syncthreads();
    }
    int excl = ps[t] - sum;
    int o0 = excl, o1 = o0 + v0, o2 = o1 + v1, o3 = o2 + v2;
    g_offsets[b] = o0;     g_offsets[b + 1] = o1;
    g_offsets[b + 2] = o2; g_offsets[b + 3] = o3;
    g_cursor[b] = o0;      g_cursor[b + 1] = o1;
    g_cursor[b + 2] = o2;  g_cursor[b + 3] = o3;
    if (t == 1023) g_offsets[NGRP] = o3 + v3;
}
__global__ void scatter_k(const int* __restrict__ jx) {
    int i = blockIdx.x * blockDim.x + threadIdx.x;
    if (i < N_ROWS) {
        int g = jx[i];
        int pos = atomicAdd(&g_cursor[g], 1);
        g_perm[pos] = i;
        g_gids[pos] = g;
    }
}

// W conversion: Wg/Wf scaled by COMP (RZ-bias compensation) then RNA-rounded; Wh plain RNA
__global__ void conv_w_k(const float4* __restrict__ Wg, const float4* __restrict__ Wf,
                         const float4* __restrict__ Wh) {
    int i = blockIdx.x * blockDim.x + threadIdx.x;
    const int per = DIM * DIM / 4;
    if (i < 3 * per) {
        int mat = i / per, j = i % per;
        const float4* src = (mat == 0) ? Wg : (mat == 1) ? Wf : Wh;
        float s = (mat == 2) ? 1.0f : COMP;
        float4 v = src[j];
        v.x = tf32r(v.x * s); v.y = tf32r(v.y * s);
        v.z = tf32r(v.z * s); v.w = tf32r(v.w * s);
        ((float4*)g_wc[mat])[j] = v;
    }
}

// y = num / (den + eps), tf32-rounded for GEMM3
__global__ void norm_y_k() {
    int i = blockIdx.x * blockDim.x + threadIdx.x;
    if (i < NGRP * DIM) g_y[i] = tf32r(g_num[i] / (g_den[i] + EPSV));
}

// out[i,:] = outg[jx[i],:]
__global__ void gather_k(const int* __restrict__ jx, float4* __restrict__ out) {
    int idx = blockIdx.x * blockDim.x + threadIdx.x;
    if (idx < N_ROWS * (DIM / 4)) {
        int i = idx >> 7;
        int c = idx & 127;
        out[idx] = ((const float4*)g_outg)[((size_t)jx[i] << 7) + c];
    }
}

extern "C" void kernel_launch(void* const* d_in, const int* in_sizes, int n_in,
                              void* d_out, int out_size) {
    const float* x  = (const float*)d_in[0];
    const float* Wf = (const float*)d_in[1];
    const float* bf = (const float*)d_in[2];
    const float* Wg = (const float*)d_in[3];
    const float* bg = (const float*)d_in[4];
    const float* Wh = (const float*)d_in[5];
    const float* bh = (const float*)d_in[6];
    const int*   jx = (const int*)d_in[7];
    float* out = (float*)d_out;
    (void)in_sizes; (void)n_in; (void)out_size;

    cudaFuncSetAttribute(gemm_fused, cudaFuncAttributeMaxDynamicSharedMemorySize, SMEM_B);
    cudaFuncSetAttribute(gemm_mma3,  cudaFuncAttributeMaxDynamicSharedMemorySize, SMEM_MAIN);

    // zero accumulators + counting sort of jx
    zero_nd_k<<<(NGRP * DIM / 4 + 255) / 256, 256>>>();
    hist_k<<<(N_ROWS + 255) / 256, 256>>>(jx);
    scan_k<<<1, 1024>>>();
    scatter_k<<<(N_ROWS + 255) / 256, 256>>>(jx);

    // W pre-conversion only (x is consumed raw, RZ-truncated by the mma, bias-compensated in W)
    conv_w_k<<<(3 * DIM * DIM / 4 + 255) / 256, 256>>>(
        (const float4*)Wg, (const float4*)Wf, (const float4*)Wh);

    // fused dual GEMM + softmax segment-reduce (M64xN64 warp tiles, 128 thr, 2 CTA/SM)
    gemm_fused<<<dim3(8, N_ROWS / 128), 128, SMEM_B>>>(x, bg, bf);

    // y = num/(den+eps)
    norm_y_k<<<(NGRP * DIM + 255) / 256, 256>>>();

    // out_group = y @ Wh^T + bh
    gemm_mma3<<<dim3(4, NGRP / 128), 256, SMEM_MAIN>>>(bh);

    // out = out_group[jx]
    gather_k<<<(N_ROWS * (DIM / 4) + 255) / 256, 256>>>(jx, (float4*)out);
}

// round 14
// speedup vs baseline: 1.3824x; 1.0559x over previous
#include <cuda_runtime.h>
#include <math.h>
#include <stdint.h>

#define N_ROWS 131072
#define DIM    512
#define NGRP   4096
#define EPSV   1e-12f

// ---------------- scratch (static device arrays; no allocation allowed) ----------------
__device__ float g_wc    [3][DIM * DIM];           // tf32-rounded Wg*(1+2^-11), Wf*(1+2^-11), Wh
__device__ float g_num   [NGRP * DIM];             // segment sums: feats*exp(l)
__device__ float g_den   [NGRP * DIM];             // segment sums: exp(l)
__device__ float g_y     [NGRP * DIM];             // normalized aggregate (tf32-rounded)
__device__ float g_outg  [NGRP * DIM];
__device__ int   g_counts [NGRP];
__device__ int   g_offsets[NGRP + 1];
__device__ int   g_cursor [NGRP];
__device__ int   g_perm   [N_ROWS];
__device__ int   g_gids   [N_ROWS];                // sorted group id per sorted row

// RZ-truncation compensation for un-prerounded A operand: E[trunc] = a*(1-2^-11)
#define COMP 1.00048828125f

// ====================== helpers ======================
__device__ __forceinline__ uint32_t smem_u32(const void* p) {
    uint32_t a;
    asm("{ .reg .u64 t; cvta.to.shared.u64 t, %1; cvt.u32.u64 %0, t; }" : "=r"(a) : "l"(p));
    return a;
}
__device__ __forceinline__ void cpa16(uint32_t dst, const void* src) {
    asm volatile("cp.async.cg.shared.global [%0], [%1], 16;" :: "r"(dst), "l"(src) : "memory");
}
__device__ __forceinline__ float tf32r(float x) {
    uint32_t u;
    asm("cvt.rna.tf32.f32 %0, %1;" : "=r"(u) : "f"(x));
    return __uint_as_float(u);
}
__device__ __forceinline__ void mma8(float* d, const uint32_t* a, uint32_t b0, uint32_t b1) {
    asm volatile(
        "mma.sync.aligned.m16n8k8.row.col.f32.tf32.tf32.f32 "
        "{%0,%1,%2,%3}, {%4,%5,%6,%7}, {%8,%9}, {%0,%1,%2,%3};"
        : "+f"(d[0]), "+f"(d[1]), "+f"(d[2]), "+f"(d[3])
        : "r"(a[0]), "r"(a[1]), "r"(a[2]), "r"(a[3]), "r"(b0), "r"(b1));
}

// ====================== GEMM tiling constants ======================
#define KC      32
#define CHUNKS  (DIM / KC)          // 16
#define SA      36                  // floats per smem row (KC + 4 pad)
#define ATF     (128 * SA)
#define STGF    (2 * ATF)           // A 128 rows + B 128 rows
// fused: 2 stages -> 73.9 KB/CTA -> 3 CTAs/SM
#define FSTG    2
#define SMEM_F  (FSTG * STGF * 4 + 512)
// gemm3: 3 stages (unchanged)
#define G3STG   3
#define SMEM_G3 (G3STG * STGF * 4)
#define EST     133                 // epilogue staging stride

// 128 rows x KC floats, contiguous rows (256 threads)
__device__ __forceinline__ void load_tile_A(uint32_t dst, const float* src, int k0, int t) {
    #pragma unroll
    for (int j = 0; j < 4; j++) {
        int idx = j * 256 + t;
        int row = idx >> 3, seg = idx & 7;
        cpa16(dst + row * (SA * 4) + seg * 16,
              src + (size_t)row * DIM + k0 + seg * 4);
    }
}
// 128 rows x KC floats, rows indirected through smem perm table (128 threads)
__device__ __forceinline__ void load_tile_Aperm128(uint32_t dst, const float* src,
                                                   const int* perm_s, int k0, int t) {
    #pragma unroll
    for (int j = 0; j < 8; j++) {
        int idx = j * 128 + t;
        int row = idx >> 3, seg = idx & 7;
        cpa16(dst + row * (SA * 4) + seg * 16,
              src + (size_t)perm_s[row] * DIM + k0 + seg * 4);
    }
}
// B tile: rows 0..63 = Wg[n0..], rows 64..127 = Wf[n0..] (128 threads)
__device__ __forceinline__ void load_tile_B2_128(uint32_t dst, const float* Wg, const float* Wf,
                                                 int n0, int k0, int t) {
    #pragma unroll
    for (int j = 0; j < 8; j++) {
        int idx = j * 128 + t;
        int row = idx >> 3, seg = idx & 7;
        const float* base = (row < 64) ? (Wg + (size_t)(n0 + row) * DIM)
                                       : (Wf + (size_t)(n0 + row - 64) * DIM);
        cpa16(dst + row * (SA * 4) + seg * 16, base + k0 + seg * 4);
    }
}

// ====================== fused dual-GEMM + softmax segment-reduce ======================
// grid (8, 1024): n0 = bx*64, m0 = by*128. A = x (raw fp32), rows via perm table.
// 128 threads, 4 warps, 2-stage pipeline, 3 CTAs/SM target.
// Warp tile: M64(wr) x N64 of ONE matrix (wmat).
__global__ __launch_bounds__(128, 3) void gemm_fused(
    const float* __restrict__ x_, const float* __restrict__ bg_, const float* __restrict__ bf_)
{
    extern __shared__ float sm[];
    const uint32_t sb = smem_u32(sm);
    int* perm_s = (int*)(sm + FSTG * STGF);
    const int t = threadIdx.x;
    const int wid = t >> 5, lid = t & 31;
    const int g = lid >> 2, c = lid & 3;
    const int wr = wid & 1;            // M half (64 rows)
    const int wmat = wid >> 1;         // 0 = Wg/logits, 1 = Wf/feats

    const int n0 = blockIdx.x * 64;
    const int m0 = blockIdx.y * 128;
    const float* Wg = g_wc[0];
    const float* Wf = g_wc[1];

    perm_s[t] = g_perm[m0 + t];
    __syncthreads();

    float acc[4][8][4];
    #pragma unroll
    for (int mf = 0; mf < 4; mf++)
        #pragma unroll
        for (int nf = 0; nf < 8; nf++)
            #pragma unroll
            for (int q = 0; q < 4; q++) acc[mf][nf][q] = 0.f;

    // prologue: chunk 0 -> stage 0
    load_tile_Aperm128(sb, x_, perm_s, 0, t);
    load_tile_B2_128(sb + ATF * 4, Wg, Wf, n0, 0, t);
    asm volatile("cp.async.commit_group;" ::: "memory");

    for (int i = 0; i < CHUNKS; i++) {
        int s = i & 1;
        if (i + 1 < CHUNKS) {
            int s1 = (i + 1) & 1;
            load_tile_Aperm128(sb + s1 * STGF * 4, x_, perm_s, (i + 1) * KC, t);
            load_tile_B2_128(sb + s1 * STGF * 4 + ATF * 4, Wg, Wf, n0, (i + 1) * KC, t);
            asm volatile("cp.async.commit_group;" ::: "memory");
            asm volatile("cp.async.wait_group 1;" ::: "memory");
        } else {
            asm volatile("cp.async.wait_group 0;" ::: "memory");
        }
        __syncthreads();

        const float* As = sm + s * STGF + (wr * 64) * SA;
        const float* Bs = sm + s * STGF + ATF + (wmat * 64) * SA;
        #pragma unroll
        for (int kk = 0; kk < KC; kk += 8) {
            uint32_t a[4][4];
            #pragma unroll
            for (int mf = 0; mf < 4; mf++) {
                const float* ap = As + (mf * 16 + g) * SA + kk + c;
                a[mf][0] = __float_as_uint(ap[0]);
                a[mf][1] = __float_as_uint(ap[8 * SA]);
                a[mf][2] = __float_as_uint(ap[4]);
                a[mf][3] = __float_as_uint(ap[8 * SA + 4]);
            }
            #pragma unroll
            for (int nf = 0; nf < 8; nf++) {
                const float* bp = Bs + (nf * 8 + g) * SA + kk + c;
                uint32_t b0 = __float_as_uint(bp[0]);
                uint32_t b1 = __float_as_uint(bp[4]);
                #pragma unroll
                for (int mf = 0; mf < 4; mf++)
                    mma8(acc[mf][nf], a[mf], b0, b1);
            }
        }
        __syncthreads();   // stage s is free for the overwrite issued next iteration
    }

    // ---- epilogue: stage (l, f) transposed [col][row], stride EST ----
    float* sl = sm;
    float* sf = sm + 64 * EST;
    int* sgid = (int*)(sm + 2 * 64 * EST);
    sgid[t] = g_gids[m0 + t];
    float* sdst = wmat ? sf : sl;
    const float* bias = wmat ? bf_ : bg_;
    #pragma unroll
    for (int nf = 0; nf < 8; nf++) {
        int cb = nf * 8 + c * 2;
        float2 bv = *(const float2*)(bias + n0 + cb);
        #pragma unroll
        for (int mf = 0; mf < 4; mf++) {
            int r0 = wr * 64 + mf * 16 + g;
            sdst[cb * EST + r0]           = acc[mf][nf][0] + bv.x;
            sdst[(cb + 1) * EST + r0]     = acc[mf][nf][1] + bv.y;
            sdst[cb * EST + r0 + 8]       = acc[mf][nf][2] + bv.x;
            sdst[(cb + 1) * EST + r0 + 8] = acc[mf][nf][3] + bv.y;
        }
    }
    __syncthreads();

    // ---- segmented reduce over sorted rows; flush per group via atomics ----
    // 128 threads = 64 cols x 2 chunks of 64 rows
    {
        int col = t & 63, q = t >> 6;
        int gcol = n0 + col;
        int r = q * 64;
        int curg = sgid[r];
        float num = 0.f, den = 0.f;
        #pragma unroll 1
        for (int k = 0; k < 64; k++, r++) {
            int gg = sgid[r];
            float l = sl[col * EST + r];
            float f = sf[col * EST + r];
            float e = __expf(l);
            if (gg != curg) {
                atomicAdd(&g_num[(size_t)curg * DIM + gcol], num);
                atomicAdd(&g_den[(size_t)curg * DIM + gcol], den);
                num = 0.f; den = 0.f; curg = gg;
            }
            num += f * e;
            den += e;
        }
        atomicAdd(&g_num[(size_t)curg * DIM + gcol], num);
        atomicAdd(&g_den[(size_t)curg * DIM + gcol], den);
    }
}

// ====================== GEMM3: out_group = y @ Wh^T + bh ======================
// grid (4, 32), 256 threads, CTA 128x128, 3-stage pipeline
__global__ __launch_bounds__(256, 2) void gemm_mma3(const float* __restrict__ bias)
{
    extern __shared__ float sm[];
    const uint32_t sb = smem_u32(sm);
    const int t = threadIdx.x;
    const int wid = t >> 5, lid = t & 31;
    const int g = lid >> 2, c = lid & 3;
    const int wr = wid & 3, wc = wid >> 2;

    const int m0 = blockIdx.y * 128, n0 = blockIdx.x * 128;
    const float* Ab = g_y + (size_t)m0 * DIM;
    const float* Wb = g_wc[2] + (size_t)n0 * DIM;
    float* C = g_outg;

    float acc[2][8][4];
    #pragma unroll
    for (int mf = 0; mf < 2; mf++)
        #pragma unroll
        for (int nf = 0; nf < 8; nf++)
            #pragma unroll
            for (int q = 0; q < 4; q++) acc[mf][nf][q] = 0.f;

    #pragma unroll
    for (int cc = 0; cc < G3STG - 1; cc++) {
        load_tile_A(sb + cc * STGF * 4,           Ab, cc * KC, t);
        load_tile_A(sb + cc * STGF * 4 + ATF * 4, Wb, cc * KC, t);
        asm volatile("cp.async.commit_group;" ::: "memory");
    }

    for (int i = 0; i < CHUNKS; i++) {
        asm volatile("cp.async.wait_group 1;" ::: "memory");
        __syncthreads();
        int nxt = i + G3STG - 1;
        if (nxt < CHUNKS) {
            int s = nxt % G3STG;
            load_tile_A(sb + s * STGF * 4,           Ab, nxt * KC, t);
            load_tile_A(sb + s * STGF * 4 + ATF * 4, Wb, nxt * KC, t);
        }
        asm volatile("cp.async.commit_group;" ::: "memory");

        const float* As = sm + (i % G3STG) * STGF + (wr * 32) * SA;
        const float* Bs = sm + (i % G3STG) * STGF + ATF + (wc * 64) * SA;
        #pragma unroll
        for (int kk = 0; kk < KC; kk += 8) {
            uint32_t a[2][4];
            #pragma unroll
            for (int mf = 0; mf < 2; mf++) {
                const float* ap = As + (mf * 16 + g) * SA + kk + c;
                a[mf][0] = __float_as_uint(ap[0]);
                a[mf][1] = __float_as_uint(ap[8 * SA]);
                a[mf][2] = __float_as_uint(ap[4]);
                a[mf][3] = __float_as_uint(ap[8 * SA + 4]);
            }
            #pragma unroll
            for (int nf = 0; nf < 8; nf++) {
                const float* bp = Bs + (nf * 8 + g) * SA + kk + c;
                uint32_t bb0 = __float_as_uint(bp[0]);
                uint32_t bb1 = __float_as_uint(bp[4]);
                mma8(acc[0][nf], a[0], bb0, bb1);
                mma8(acc[1][nf], a[1], bb0, bb1);
            }
        }
    }

    const int rowb = m0 + wr * 32 + g;
    const int colb = n0 + wc * 64 + c * 2;
    #pragma unroll
    for (int nf = 0; nf < 8; nf++) {
        int col = colb + nf * 8;
        float bv0 = bias[col], bv1 = bias[col + 1];
        #pragma unroll
        for (int mf = 0; mf < 2; mf++) {
            int r0 = rowb + mf * 16;
            float2 v;
            v.x = acc[mf][nf][0] + bv0; v.y = acc[mf][nf][1] + bv1;
            *(float2*)(C + (size_t)r0 * DIM + col) = v;
            v.x = acc[mf][nf][2] + bv0; v.y = acc[mf][nf][3] + bv1;
            *(float2*)(C + (size_t)(r0 + 8) * DIM + col) = v;
        }
    }
}

// ---------------- small kernels ----------------
// merged: zero num/den/counts + W tf32 conversion (Wg/Wf scaled by COMP, Wh plain)
__global__ void conv_w_zero_k(const float4* __restrict__ Wg, const float4* __restrict__ Wf,
                              const float4* __restrict__ Wh) {
    int i = blockIdx.x * blockDim.x + threadIdx.x;
    const int per = DIM * DIM / 4;
    if (i < 3 * per) {
        int mat = i / per, j = i % per;
        const float4* src = (mat == 0) ? Wg : (mat == 1) ? Wf : Wh;
        float s = (mat == 2) ? 1.0f : COMP;
        float4 v = src[j];
        v.x = tf32r(v.x * s); v.y = tf32r(v.y * s);
        v.z = tf32r(v.z * s); v.w = tf32r(v.w * s);
        ((float4*)g_wc[mat])[j] = v;
    }
    if (i < NGRP * DIM / 4) {
        float4 z = make_float4(0.f, 0.f, 0.f, 0.f);
        ((float4*)g_num)[i] = z;
        ((float4*)g_den)[i] = z;
    }
    if (i < NGRP) g_counts[i] = 0;
}
__global__ void hist_k(const int* __restrict__ jx) {
    int i = blockIdx.x * blockDim.x + threadIdx.x;
    if (i < N_ROWS) atomicAdd(&g_counts[jx[i]], 1);
}
__global__ void scan_k() {
    __shared__ int s[NGRP];
    __shared__ int ps[1024];
    int t = threadIdx.x;
    for (int i = t; i < NGRP; i += 1024) s[i] = g_counts[i];
    __syncthreads();
    int b = t * 4;
    int v0 = s[b], v1 = s[b + 1], v2 = s[b + 2], v3 = s[b + 3];
    int sum = v0 + v1 + v2 + v3;
    ps[t] = sum;
    __syncthreads();
    #pragma unroll
    for (int off = 1; off < 1024; off <<= 1) {
        int x = (t >= off) ? ps[t - off] : 0;
        __syncthreads();
        ps[t] += x;
        __syncthreads();
    }
    int excl = ps[t] - sum;
    int o0 = excl, o1 = o0 + v0, o2 = o1 + v1, o3 = o2 + v2;
    g_offsets[b] = o0;     g_offsets[b + 1] = o1;
    g_offsets[b + 2] = o2; g_offsets[b + 3] = o3;
    g_cursor[b] = o0;      g_cursor[b + 1] = o1;
    g_cursor[b + 2] = o2;  g_cursor[b + 3] = o3;
    if (t == 1023) g_offsets[NGRP] = o3 + v3;
}
__global__ void scatter_k(const int* __restrict__ jx) {
    int i = blockIdx.x * blockDim.x + threadIdx.x;
    if (i < N_ROWS) {
        int g = jx[i];
        int pos = atomicAdd(&g_cursor[g], 1);
        g_perm[pos] = i;
        g_gids[pos] = g;
    }
}

// y = num / (den + eps), tf32-rounded for GEMM3
__global__ void norm_y_k() {
    int i = blockIdx.x * blockDim.x + threadIdx.x;
    if (i < NGRP * DIM) g_y[i] = tf32r(g_num[i] / (g_den[i] + EPSV));
}

// out[i,:] = outg[jx[i],:]
__global__ void gather_k(const int* __restrict__ jx, float4* __restrict__ out) {
    int idx = blockIdx.x * blockDim.x + threadIdx.x;
    if (idx < N_ROWS * (DIM / 4)) {
        int i = idx >> 7;
        int c = idx & 127;
        out[idx] = ((const float4*)g_outg)[((size_t)jx[i] << 7) + c];
    }
}

extern "C" void kernel_launch(void* const* d_in, const int* in_sizes, int n_in,
                              void* d_out, int out_size) {
    const float* x  = (const float*)d_in[0];
    const float* Wf = (const float*)d_in[1];
    const float* bf = (const float*)d_in[2];
    const float* Wg = (const float*)d_in[3];
    const float* bg = (const float*)d_in[4];
    const float* Wh = (const float*)d_in[5];
    const float* bh = (const float*)d_in[6];
    const int*   jx = (const int*)d_in[7];
    float* out = (float*)d_out;
    (void)in_sizes; (void)n_in; (void)out_size;

    cudaFuncSetAttribute(gemm_fused, cudaFuncAttributeMaxDynamicSharedMemorySize, SMEM_F);
    cudaFuncSetAttribute(gemm_mma3,  cudaFuncAttributeMaxDynamicSharedMemorySize, SMEM_G3);

    // zero accumulators + W pre-conversion (merged), then counting sort of jx
    conv_w_zero_k<<<(NGRP * DIM / 4 + 255) / 256, 256>>>(
        (const float4*)Wg, (const float4*)Wf, (const float4*)Wh);
    hist_k<<<(N_ROWS + 255) / 256, 256>>>(jx);
    scan_k<<<1, 1024>>>();
    scatter_k<<<(N_ROWS + 255) / 256, 256>>>(jx);

    // fused dual GEMM + softmax segment-reduce (2-stage pipeline, 3 CTAs/SM)
    gemm_fused<<<dim3(8, N_ROWS / 128), 128, SMEM_F>>>(x, bg, bf);

    // y = num/(den+eps)
    norm_y_k<<<(NGRP * DIM + 255) / 256, 256>>>();

    // out_group = y @ Wh^T + bh
    gemm_mma3<<<dim3(4, NGRP / 128), 256, SMEM_G3>>>(bh);

    // out = out_group[jx]
    gather_k<<<(N_ROWS * (DIM / 4) + 255) / 256, 256>>>(jx, (float4*)out);
}